// round 2
// baseline (speedup 1.0000x reference)
#include <cuda_runtime.h>
#include <math.h>

#define DIM 1024
#define NH 16
#define HD 64
#define HIDDEN 4096
#define SQ 2048
#define BB 4
#define BTOK (BB*SQ)   // 8192 tokens

// ---------------- scratch (static device globals; no runtime allocation) ----------------
__device__ float g_xn[(size_t)BTOK * DIM];
__device__ float g_q [(size_t)BTOK * DIM];
__device__ float g_k [(size_t)BTOK * DIM];
__device__ float g_v [(size_t)BTOK * DIM];
__device__ float g_att[(size_t)BTOK * DIM];
__device__ float g_x1[(size_t)BTOK * DIM];
__device__ float g_h [(size_t)BTOK * HIDDEN];

// ---------------- RMSNorm ----------------
// one block per row (1024 floats), 256 threads, float4
__global__ void __launch_bounds__(256) rmsnorm_kernel(const float* __restrict__ x,
                                                      const float* __restrict__ g,
                                                      float* __restrict__ out)
{
    int row = blockIdx.x;
    int t = threadIdx.x;
    const float4* xr = (const float4*)(x + (size_t)row * DIM);
    float4 xv = xr[t];
    float ss = xv.x*xv.x + xv.y*xv.y + xv.z*xv.z + xv.w*xv.w;
    #pragma unroll
    for (int o = 16; o; o >>= 1) ss += __shfl_xor_sync(0xffffffffu, ss, o);
    __shared__ float sred[8];
    if ((t & 31) == 0) sred[t >> 5] = ss;
    __syncthreads();
    if (t < 8) {
        float s = sred[t];
        #pragma unroll
        for (int o = 4; o; o >>= 1) s += __shfl_xor_sync(0xffu, s, o);
        if (t == 0) sred[0] = s;
    }
    __syncthreads();
    float rr = rsqrtf(sred[0] * (1.0f / DIM) + 1e-6f);
    float4 gv = ((const float4*)g)[t];
    float4 ov = make_float4(xv.x*rr*gv.x, xv.y*rr*gv.y, xv.z*rr*gv.z, xv.w*rr*gv.w);
    ((float4*)(out + (size_t)row * DIM))[t] = ov;
}

// ---------------- GEMM: C[M,N] = A[M,K] @ B[N,K]^T + bias (+relu) (+residual) ----------------
// BM=BN=128, BK=8, 256 threads, 8x8 per-thread microtile, float4 global loads.
template<int RELU, int RES>
__global__ void __launch_bounds__(256) gemm_bias_kernel(
    const float* __restrict__ A, const float* __restrict__ B,
    const float* __restrict__ bias, const float* __restrict__ res,
    float* __restrict__ C, int M, int N, int K)
{
    __shared__ float As[8][128];
    __shared__ float Bs[8][128];
    int tid = threadIdx.x;
    int m0 = blockIdx.y * 128;
    int n0 = blockIdx.x * 128;
    int lm = tid >> 1;           // 0..127
    int lk = (tid & 1) * 4;      // 0 or 4
    const float* Aptr = A + (size_t)(m0 + lm) * K + lk;
    const float* Bptr = B + (size_t)(n0 + lm) * K + lk;
    int ty = tid >> 4, tx = tid & 15;

    float acc[8][8];
    #pragma unroll
    for (int i = 0; i < 8; i++)
        #pragma unroll
        for (int j = 0; j < 8; j++) acc[i][j] = 0.f;

    for (int k0 = 0; k0 < K; k0 += 8) {
        float4 av = *(const float4*)(Aptr + k0);
        float4 bv = *(const float4*)(Bptr + k0);
        As[lk+0][lm] = av.x; As[lk+1][lm] = av.y; As[lk+2][lm] = av.z; As[lk+3][lm] = av.w;
        Bs[lk+0][lm] = bv.x; Bs[lk+1][lm] = bv.y; Bs[lk+2][lm] = bv.z; Bs[lk+3][lm] = bv.w;
        __syncthreads();
        #pragma unroll
        for (int k = 0; k < 8; k++) {
            float a[8], b[8];
            *(float4*)(a)     = *(const float4*)&As[k][ty*8];
            *(float4*)(a + 4) = *(const float4*)&As[k][ty*8 + 4];
            *(float4*)(b)     = *(const float4*)&Bs[k][tx*8];
            *(float4*)(b + 4) = *(const float4*)&Bs[k][tx*8 + 4];
            #pragma unroll
            for (int i = 0; i < 8; i++)
                #pragma unroll
                for (int j = 0; j < 8; j++)
                    acc[i][j] += a[i] * b[j];
        }
        __syncthreads();
    }

    #pragma unroll
    for (int i = 0; i < 8; i++) {
        int m = m0 + ty*8 + i;
        float* crow = C + (size_t)m * N + n0 + tx*8;
        const float* rrow = RES ? (res + (size_t)m * N + n0 + tx*8) : nullptr;
        #pragma unroll
        for (int j = 0; j < 8; j++) {
            float vv = acc[i][j] + bias[n0 + tx*8 + j];
            if (RELU) vv = fmaxf(vv, 0.f);
            if (RES)  vv += rrow[j];
            crow[j] = vv;
        }
    }
}

// ---------------- Flash attention (fp32), Br=Bc=64, head_dim=64 ----------------
// grid: (B*NH, SQ/64). block: 256 threads (16x16 of 4x4 microtiles).
// Dynamic smem layout (floats, rows padded to 65):
//   Qs[64][65] | Kt[64][65] (Kt[d][j]) | Vs[64][65] | Ss[64][65] | m[64] l[64] a[64] | msk[64]
#define ATT_SMEM_FLOATS (4*64*65 + 3*64 + 64)
#define ATT_SMEM_BYTES  (ATT_SMEM_FLOATS * 4)

__global__ void __launch_bounds__(256) attn_kernel(
    const float* __restrict__ Q, const float* __restrict__ K, const float* __restrict__ V,
    const int* __restrict__ emask, float* __restrict__ O)
{
    extern __shared__ float sm[];
    float (*Qs)[65] = (float(*)[65])(sm);
    float (*Kt)[65] = (float(*)[65])(sm + 64*65);
    float (*Vs)[65] = (float(*)[65])(sm + 2*64*65);
    float (*Ss)[65] = (float(*)[65])(sm + 3*64*65);
    float* mrow = sm + 4*64*65;
    float* lrow = mrow + 64;
    float* arow = lrow + 64;
    int*   msk  = (int*)(arow + 64);

    int bh = blockIdx.x;           // 0..63
    int qb = blockIdx.y;           // 0..31
    int b = bh >> 4, h = bh & 15;
    const size_t base = (size_t)b * SQ * DIM + (size_t)h * HD;
    int tid = threadIdx.x;
    int ty = tid >> 4, tx = tid & 15;

    // load Q tile, pre-scaled by 1/sqrt(64)=0.125
    for (int idx = tid; idx < 64*64; idx += 256) {
        int i = idx >> 6, d = idx & 63;
        Qs[i][d] = Q[base + (size_t)(qb*64 + i) * DIM + d] * 0.125f;
    }
    if (tid < 64) { mrow[tid] = -1e30f; lrow[tid] = 0.f; }

    float o[4][4];
    #pragma unroll
    for (int r = 0; r < 4; r++)
        #pragma unroll
        for (int c = 0; c < 4; c++) o[r][c] = 0.f;

    for (int kb = 0; kb < SQ/64; kb++) {
        __syncthreads();  // prev-iter consumers done (also covers Q load / m,l init on iter 0)
        for (int idx = tid; idx < 64*64; idx += 256) {
            int j = idx >> 6, d = idx & 63;
            Kt[d][j] = K[base + (size_t)(kb*64 + j) * DIM + d];
            Vs[j][d] = V[base + (size_t)(kb*64 + j) * DIM + d];
        }
        if (tid < 64) msk[tid] = emask[b * SQ + kb*64 + tid];
        __syncthreads();

        // S = Q @ K^T (scaled; Q pre-scaled)
        float s[4][4];
        #pragma unroll
        for (int r = 0; r < 4; r++)
            #pragma unroll
            for (int c = 0; c < 4; c++) s[r][c] = 0.f;
        #pragma unroll 8
        for (int d = 0; d < 64; d++) {
            float a0 = Qs[ty*4+0][d], a1 = Qs[ty*4+1][d], a2 = Qs[ty*4+2][d], a3 = Qs[ty*4+3][d];
            float b0 = Kt[d][tx*4+0], b1 = Kt[d][tx*4+1], b2 = Kt[d][tx*4+2], b3 = Kt[d][tx*4+3];
            s[0][0] += a0*b0; s[0][1] += a0*b1; s[0][2] += a0*b2; s[0][3] += a0*b3;
            s[1][0] += a1*b0; s[1][1] += a1*b1; s[1][2] += a1*b2; s[1][3] += a1*b3;
            s[2][0] += a2*b0; s[2][1] += a2*b1; s[2][2] += a2*b2; s[2][3] += a2*b3;
            s[3][0] += a3*b0; s[3][1] += a3*b1; s[3][2] += a3*b2; s[3][3] += a3*b3;
        }
        #pragma unroll
        for (int r = 0; r < 4; r++)
            #pragma unroll
            for (int c = 0; c < 4; c++)
                Ss[ty*4+r][tx*4+c] = (msk[tx*4+c] != 0) ? s[r][c] : -1e9f;
        __syncthreads();

        // online softmax per row (threads 0..63 each own a row)
        if (tid < 64) {
            float m = mrow[tid];
            float rmax = -1e30f;
            #pragma unroll 8
            for (int j = 0; j < 64; j++) rmax = fmaxf(rmax, Ss[tid][j]);
            float mn = fmaxf(m, rmax);
            float alpha = __expf(m - mn);
            float rs = 0.f;
            #pragma unroll 8
            for (int j = 0; j < 64; j++) {
                float p = __expf(Ss[tid][j] - mn);
                Ss[tid][j] = p;
                rs += p;
            }
            lrow[tid] = lrow[tid] * alpha + rs;
            mrow[tid] = mn;
            arow[tid] = alpha;
        }
        __syncthreads();

        // O = O*alpha + P @ V
        float al[4];
        #pragma unroll
        for (int r = 0; r < 4; r++) al[r] = arow[ty*4 + r];
        #pragma unroll
        for (int r = 0; r < 4; r++)
            #pragma unroll
            for (int c = 0; c < 4; c++) o[r][c] *= al[r];
        #pragma unroll 8
        for (int j = 0; j < 64; j++) {
            float a0 = Ss[ty*4+0][j], a1 = Ss[ty*4+1][j], a2 = Ss[ty*4+2][j], a3 = Ss[ty*4+3][j];
            float b0 = Vs[j][tx*4+0], b1 = Vs[j][tx*4+1], b2 = Vs[j][tx*4+2], b3 = Vs[j][tx*4+3];
            o[0][0] += a0*b0; o[0][1] += a0*b1; o[0][2] += a0*b2; o[0][3] += a0*b3;
            o[1][0] += a1*b0; o[1][1] += a1*b1; o[1][2] += a1*b2; o[1][3] += a1*b3;
            o[2][0] += a2*b0; o[2][1] += a2*b1; o[2][2] += a2*b2; o[2][3] += a2*b3;
            o[3][0] += a3*b0; o[3][1] += a3*b1; o[3][2] += a3*b2; o[3][3] += a3*b3;
        }
    }
    __syncthreads();

    #pragma unroll
    for (int r = 0; r < 4; r++) {
        float inv_l = 1.0f / lrow[ty*4 + r];
        #pragma unroll
        for (int c = 0; c < 4; c++) {
            O[base + (size_t)(qb*64 + ty*4 + r) * DIM + (tx*4 + c)] = o[r][c] * inv_l;
        }
    }
}

// ---------------- launch ----------------
extern "C" void kernel_launch(void* const* d_in, const int* in_sizes, int n_in,
                              void* d_out, int out_size)
{
    const float* x    = (const float*)d_in[0];
    const int*   em   = (const int*)  d_in[1];
    const float* wq   = (const float*)d_in[2];
    const float* bq   = (const float*)d_in[3];
    const float* wk   = (const float*)d_in[4];
    const float* bk   = (const float*)d_in[5];
    const float* wv   = (const float*)d_in[6];
    const float* bv   = (const float*)d_in[7];
    const float* wo   = (const float*)d_in[8];
    const float* bo   = (const float*)d_in[9];
    const float* w1   = (const float*)d_in[10];
    const float* b1   = (const float*)d_in[11];
    const float* w2   = (const float*)d_in[12];
    const float* b2   = (const float*)d_in[13];
    const float* ga   = (const float*)d_in[14];
    const float* gf   = (const float*)d_in[15];
    float* out = (float*)d_out;

    float *xn, *q, *k, *v, *att, *x1, *h;
    cudaGetSymbolAddress((void**)&xn,  g_xn);
    cudaGetSymbolAddress((void**)&q,   g_q);
    cudaGetSymbolAddress((void**)&k,   g_k);
    cudaGetSymbolAddress((void**)&v,   g_v);
    cudaGetSymbolAddress((void**)&att, g_att);
    cudaGetSymbolAddress((void**)&x1,  g_x1);
    cudaGetSymbolAddress((void**)&h,   g_h);

    // idempotent, not a stream op; called every time (no static guards allowed)
    cudaFuncSetAttribute(attn_kernel, cudaFuncAttributeMaxDynamicSharedMemorySize, ATT_SMEM_BYTES);

    dim3 gProj(DIM / 128, BTOK / 128);       // N=1024 tiles x M=8192 tiles
    dim3 gFfn1(HIDDEN / 128, BTOK / 128);    // N=4096

    // 1. xn = rmsnorm(x, g_attn)
    rmsnorm_kernel<<<BTOK, 256>>>(x, ga, xn);
    // 2-4. Q,K,V projections
    gemm_bias_kernel<0,0><<<gProj, 256>>>(xn, wq, bq, nullptr, q, BTOK, DIM, DIM);
    gemm_bias_kernel<0,0><<<gProj, 256>>>(xn, wk, bk, nullptr, k, BTOK, DIM, DIM);
    gemm_bias_kernel<0,0><<<gProj, 256>>>(xn, wv, bv, nullptr, v, BTOK, DIM, DIM);
    // 5. flash attention
    attn_kernel<<<dim3(BB*NH, SQ/64), 256, ATT_SMEM_BYTES>>>(q, k, v, em, att);
    // 6. x1 = x + att @ wo^T + bo
    gemm_bias_kernel<0,1><<<gProj, 256>>>(att, wo, bo, x, x1, BTOK, DIM, DIM);
    // 7. xn = rmsnorm(x1, g_ffn)
    rmsnorm_kernel<<<BTOK, 256>>>(x1, gf, xn);
    // 8. h = relu(xn @ w1^T + b1)
    gemm_bias_kernel<1,0><<<gFfn1, 256>>>(xn, w1, b1, nullptr, h, BTOK, HIDDEN, DIM);
    // 9. out = x1 + h @ w2^T + b2
    gemm_bias_kernel<0,1><<<gProj, 256>>>(h, w2, b2, x1, out, BTOK, DIM, HIDDEN);
}

// round 3
// speedup vs baseline: 1.4384x; 1.4384x over previous
#include <cuda_runtime.h>
#include <cuda_bf16.h>
#include <math.h>
#include <stdint.h>

#define DIM 1024
#define NH 16
#define HD 64
#define HIDDEN 4096
#define SQ 2048
#define BB 4
#define BTOK (BB*SQ)   // 8192 tokens

// ---------------- scratch ----------------
__device__ float g_xn[(size_t)BTOK * DIM];
__device__ float g_q [(size_t)BTOK * DIM];
__device__ float g_k [(size_t)BTOK * DIM];
__device__ float g_v [(size_t)BTOK * DIM];
__device__ float g_att[(size_t)BTOK * DIM];
__device__ float g_x1[(size_t)BTOK * DIM];
__device__ float g_h [(size_t)BTOK * HIDDEN];

// ---------------- RMSNorm (unchanged, verified) ----------------
__global__ void __launch_bounds__(256) rmsnorm_kernel(const float* __restrict__ x,
                                                      const float* __restrict__ g,
                                                      float* __restrict__ out)
{
    int row = blockIdx.x;
    int t = threadIdx.x;
    const float4* xr = (const float4*)(x + (size_t)row * DIM);
    float4 xv = xr[t];
    float ss = xv.x*xv.x + xv.y*xv.y + xv.z*xv.z + xv.w*xv.w;
    #pragma unroll
    for (int o = 16; o; o >>= 1) ss += __shfl_xor_sync(0xffffffffu, ss, o);
    __shared__ float sred[8];
    if ((t & 31) == 0) sred[t >> 5] = ss;
    __syncthreads();
    if (t < 8) {
        float s = sred[t];
        #pragma unroll
        for (int o = 4; o; o >>= 1) s += __shfl_xor_sync(0xffu, s, o);
        if (t == 0) sred[0] = s;
    }
    __syncthreads();
    float rr = rsqrtf(sred[0] * (1.0f / DIM) + 1e-6f);
    float4 gv = ((const float4*)g)[t];
    float4 ov = make_float4(xv.x*rr*gv.x, xv.y*rr*gv.y, xv.z*rr*gv.z, xv.w*rr*gv.w);
    ((float4*)(out + (size_t)row * DIM))[t] = ov;
}

// ---------------- Tensor-core GEMM (bf16x2 split, mma.sync m16n8k16) ----------------
// C[M,N] = A[M,K] @ B[N,K]^T + bias (+relu) (+residual)
// Block 128x128, BK=32, 256 threads (8 warps, 2x4 of 64x32 warp tiles), double-buffered.
// Accuracy: x = hi + lo (bf16 each); acc += aH*bH + aH*bL + aL*bH  (err ~2^-16).

#define GBK 32
#define GPAD 40                         // bf16 row stride (80B; conflict-free for ldmatrix)
#define G_A_ELEMS (128*GPAD)
#define G_STAGE_BYTES (4 * G_A_ELEMS * 2)   // AsH,AsL,BsH,BsL
#define G_SMEM_BYTES (2 * G_STAGE_BYTES)    // 80 KB

__device__ __forceinline__ uint32_t smem_u32(const void* p) {
    return (uint32_t)__cvta_generic_to_shared(p);
}

__device__ __forceinline__ void ldm_x4(uint32_t& r0, uint32_t& r1, uint32_t& r2, uint32_t& r3, uint32_t addr) {
    asm volatile("ldmatrix.sync.aligned.m8n8.x4.shared.b16 {%0,%1,%2,%3}, [%4];"
                 : "=r"(r0), "=r"(r1), "=r"(r2), "=r"(r3) : "r"(addr));
}
__device__ __forceinline__ void ldm_x2(uint32_t& r0, uint32_t& r1, uint32_t addr) {
    asm volatile("ldmatrix.sync.aligned.m8n8.x2.shared.b16 {%0,%1}, [%2];"
                 : "=r"(r0), "=r"(r1) : "r"(addr));
}
__device__ __forceinline__ void mma_bf16(float* c, const uint32_t* a, const uint32_t* b) {
    asm volatile("mma.sync.aligned.m16n8k16.row.col.f32.bf16.bf16.f32 "
                 "{%0,%1,%2,%3},{%4,%5,%6,%7},{%8,%9},{%0,%1,%2,%3};"
                 : "+f"(c[0]), "+f"(c[1]), "+f"(c[2]), "+f"(c[3])
                 : "r"(a[0]), "r"(a[1]), "r"(a[2]), "r"(a[3]), "r"(b[0]), "r"(b[1]));
}

// convert float4 -> 4x(hi,lo) bf16, store 2x bfloat162 to each of hi/lo
__device__ __forceinline__ void split_store(__nv_bfloat16* hi, __nv_bfloat16* lo, float4 v) {
    __nv_bfloat16 h0 = __float2bfloat16(v.x);
    __nv_bfloat16 h1 = __float2bfloat16(v.y);
    __nv_bfloat16 h2 = __float2bfloat16(v.z);
    __nv_bfloat16 h3 = __float2bfloat16(v.w);
    __nv_bfloat16 l0 = __float2bfloat16(v.x - __bfloat162float(h0));
    __nv_bfloat16 l1 = __float2bfloat16(v.y - __bfloat162float(h1));
    __nv_bfloat16 l2 = __float2bfloat16(v.z - __bfloat162float(h2));
    __nv_bfloat16 l3 = __float2bfloat16(v.w - __bfloat162float(h3));
    __nv_bfloat162 p;
    p.x = h0; p.y = h1; ((__nv_bfloat162*)hi)[0] = p;
    p.x = h2; p.y = h3; ((__nv_bfloat162*)hi)[1] = p;
    p.x = l0; p.y = l1; ((__nv_bfloat162*)lo)[0] = p;
    p.x = l2; p.y = l3; ((__nv_bfloat162*)lo)[1] = p;
}

template<int RELU, int RES>
__global__ void __launch_bounds__(256) gemm_tc_kernel(
    const float* __restrict__ A, const float* __restrict__ B,
    const float* __restrict__ bias, const float* __restrict__ res,
    float* __restrict__ C, int M, int N, int K)
{
    extern __shared__ char dynsm[];
    const int tid = threadIdx.x;
    const int lane = tid & 31;
    const int wid = tid >> 5;
    const int wm = wid >> 2;        // 0..1
    const int wn = wid & 3;         // 0..3
    const int m0 = blockIdx.y * 128;
    const int n0 = blockIdx.x * 128;

    // loader mapping: each thread loads 4 float4 of A and 4 float4 of B per stage
    const int lr = tid >> 1;            // row 0..127
    const int lc = (tid & 1) * 16;      // col base 0 or 16 (floats)

    // stage base pointers (bf16)
    __nv_bfloat16* sAH[2]; __nv_bfloat16* sAL[2];
    __nv_bfloat16* sBH[2]; __nv_bfloat16* sBL[2];
    #pragma unroll
    for (int s = 0; s < 2; s++) {
        char* base = dynsm + s * G_STAGE_BYTES;
        sAH[s] = (__nv_bfloat16*)(base);
        sAL[s] = (__nv_bfloat16*)(base + G_A_ELEMS*2);
        sBH[s] = (__nv_bfloat16*)(base + G_A_ELEMS*4);
        sBL[s] = (__nv_bfloat16*)(base + G_A_ELEMS*6);
    }

    float acc[4][4][4];
    #pragma unroll
    for (int i = 0; i < 4; i++)
        #pragma unroll
        for (int j = 0; j < 4; j++)
            #pragma unroll
            for (int c = 0; c < 4; c++) acc[i][j][c] = 0.f;

    const int nk = K / GBK;

    // ---- preload stage 0 ----
    {
        const float* Ap = A + (size_t)(m0 + lr) * K + lc;
        const float* Bp = B + (size_t)(n0 + lr) * K + lc;
        #pragma unroll
        for (int j = 0; j < 4; j++) {
            float4 av = *(const float4*)(Ap + j*4);
            float4 bv = *(const float4*)(Bp + j*4);
            split_store(&sAH[0][lr*GPAD + lc + j*4], &sAL[0][lr*GPAD + lc + j*4], av);
            split_store(&sBH[0][lr*GPAD + lc + j*4], &sBL[0][lr*GPAD + lc + j*4], bv);
        }
    }
    __syncthreads();

    // ldmatrix lane address components
    const int a_row = lane & 15;
    const int a_col = (lane >> 4) << 3;      // 0 or 8
    const int b_row = lane & 7;
    const int b_col = ((lane >> 3) & 1) << 3;

    for (int kb = 0; kb < nk; kb++) {
        const int cur = kb & 1;
        const bool pf = (kb + 1) < nk;
        float4 apre[4], bpre[4];
        if (pf) {
            const float* Ap = A + (size_t)(m0 + lr) * K + (kb+1)*GBK + lc;
            const float* Bp = B + (size_t)(n0 + lr) * K + (kb+1)*GBK + lc;
            #pragma unroll
            for (int j = 0; j < 4; j++) { apre[j] = *(const float4*)(Ap + j*4); bpre[j] = *(const float4*)(Bp + j*4); }
        }

        const uint32_t baH = smem_u32(sAH[cur]);
        const uint32_t baL = smem_u32(sAL[cur]);
        const uint32_t bbH = smem_u32(sBH[cur]);
        const uint32_t bbL = smem_u32(sBL[cur]);

        #pragma unroll
        for (int ks = 0; ks < 2; ks++) {
            const int k0 = ks * 16;
            uint32_t aH[4][4], aL[4][4], bH[4][2], bL[4][2];
            #pragma unroll
            for (int mi = 0; mi < 4; mi++) {
                uint32_t off = (uint32_t)((wm*64 + mi*16 + a_row) * GPAD + k0 + a_col) * 2;
                ldm_x4(aH[mi][0], aH[mi][1], aH[mi][2], aH[mi][3], baH + off);
                ldm_x4(aL[mi][0], aL[mi][1], aL[mi][2], aL[mi][3], baL + off);
            }
            #pragma unroll
            for (int ni = 0; ni < 4; ni++) {
                uint32_t off = (uint32_t)((wn*32 + ni*8 + b_row) * GPAD + k0 + b_col) * 2;
                ldm_x2(bH[ni][0], bH[ni][1], bbH + off);
                ldm_x2(bL[ni][0], bL[ni][1], bbL + off);
            }
            #pragma unroll
            for (int mi = 0; mi < 4; mi++)
                #pragma unroll
                for (int ni = 0; ni < 4; ni++) {
                    mma_bf16(acc[mi][ni], aH[mi], bH[ni]);
                    mma_bf16(acc[mi][ni], aH[mi], bL[ni]);
                    mma_bf16(acc[mi][ni], aL[mi], bH[ni]);
                }
        }
        __syncthreads();
        if (pf) {
            const int nxt = cur ^ 1;
            #pragma unroll
            for (int j = 0; j < 4; j++) {
                split_store(&sAH[nxt][lr*GPAD + lc + j*4], &sAL[nxt][lr*GPAD + lc + j*4], apre[j]);
                split_store(&sBH[nxt][lr*GPAD + lc + j*4], &sBL[nxt][lr*GPAD + lc + j*4], bpre[j]);
            }
            __syncthreads();
        }
    }

    // ---- epilogue ----
    const int g = lane >> 2, tg = lane & 3;
    #pragma unroll
    for (int mi = 0; mi < 4; mi++) {
        const int row = m0 + wm*64 + mi*16 + g;
        #pragma unroll
        for (int ni = 0; ni < 4; ni++) {
            const int col = n0 + wn*32 + ni*8 + tg*2;
            float bv0 = bias[col], bv1 = bias[col + 1];
            float v0 = acc[mi][ni][0] + bv0, v1 = acc[mi][ni][1] + bv1;
            float v2 = acc[mi][ni][2] + bv0, v3 = acc[mi][ni][3] + bv1;
            if (RELU) { v0 = fmaxf(v0, 0.f); v1 = fmaxf(v1, 0.f); v2 = fmaxf(v2, 0.f); v3 = fmaxf(v3, 0.f); }
            if (RES) {
                const float2 r0 = *(const float2*)(res + (size_t)row * N + col);
                const float2 r1 = *(const float2*)(res + (size_t)(row + 8) * N + col);
                v0 += r0.x; v1 += r0.y; v2 += r1.x; v3 += r1.y;
            }
            float2 o0 = make_float2(v0, v1), o1 = make_float2(v2, v3);
            *(float2*)(C + (size_t)row * N + col) = o0;
            *(float2*)(C + (size_t)(row + 8) * N + col) = o1;
        }
    }
}

// ---------------- Flash attention (fp32 SIMT, unchanged & verified) ----------------
#define ATT_SMEM_FLOATS (4*64*65 + 3*64 + 64)
#define ATT_SMEM_BYTES  (ATT_SMEM_FLOATS * 4)

__global__ void __launch_bounds__(256) attn_kernel(
    const float* __restrict__ Q, const float* __restrict__ K, const float* __restrict__ V,
    const int* __restrict__ emask, float* __restrict__ O)
{
    extern __shared__ float sm[];
    float (*Qs)[65] = (float(*)[65])(sm);
    float (*Kt)[65] = (float(*)[65])(sm + 64*65);
    float (*Vs)[65] = (float(*)[65])(sm + 2*64*65);
    float (*Ss)[65] = (float(*)[65])(sm + 3*64*65);
    float* mrow = sm + 4*64*65;
    float* lrow = mrow + 64;
    float* arow = lrow + 64;
    int*   msk  = (int*)(arow + 64);

    int bh = blockIdx.x;
    int qb = blockIdx.y;
    int b = bh >> 4, h = bh & 15;
    const size_t base = (size_t)b * SQ * DIM + (size_t)h * HD;
    int tid = threadIdx.x;
    int ty = tid >> 4, tx = tid & 15;

    for (int idx = tid; idx < 64*64; idx += 256) {
        int i = idx >> 6, d = idx & 63;
        Qs[i][d] = Q[base + (size_t)(qb*64 + i) * DIM + d] * 0.125f;
    }
    if (tid < 64) { mrow[tid] = -1e30f; lrow[tid] = 0.f; }

    float o[4][4];
    #pragma unroll
    for (int r = 0; r < 4; r++)
        #pragma unroll
        for (int c = 0; c < 4; c++) o[r][c] = 0.f;

    for (int kb = 0; kb < SQ/64; kb++) {
        __syncthreads();
        for (int idx = tid; idx < 64*64; idx += 256) {
            int j = idx >> 6, d = idx & 63;
            Kt[d][j] = K[base + (size_t)(kb*64 + j) * DIM + d];
            Vs[j][d] = V[base + (size_t)(kb*64 + j) * DIM + d];
        }
        if (tid < 64) msk[tid] = emask[b * SQ + kb*64 + tid];
        __syncthreads();

        float s[4][4];
        #pragma unroll
        for (int r = 0; r < 4; r++)
            #pragma unroll
            for (int c = 0; c < 4; c++) s[r][c] = 0.f;
        #pragma unroll 8
        for (int d = 0; d < 64; d++) {
            float a0 = Qs[ty*4+0][d], a1 = Qs[ty*4+1][d], a2 = Qs[ty*4+2][d], a3 = Qs[ty*4+3][d];
            float b0 = Kt[d][tx*4+0], b1 = Kt[d][tx*4+1], b2 = Kt[d][tx*4+2], b3 = Kt[d][tx*4+3];
            s[0][0] += a0*b0; s[0][1] += a0*b1; s[0][2] += a0*b2; s[0][3] += a0*b3;
            s[1][0] += a1*b0; s[1][1] += a1*b1; s[1][2] += a1*b2; s[1][3] += a1*b3;
            s[2][0] += a2*b0; s[2][1] += a2*b1; s[2][2] += a2*b2; s[2][3] += a2*b3;
            s[3][0] += a3*b0; s[3][1] += a3*b1; s[3][2] += a3*b2; s[3][3] += a3*b3;
        }
        #pragma unroll
        for (int r = 0; r < 4; r++)
            #pragma unroll
            for (int c = 0; c < 4; c++)
                Ss[ty*4+r][tx*4+c] = (msk[tx*4+c] != 0) ? s[r][c] : -1e9f;
        __syncthreads();

        if (tid < 64) {
            float m = mrow[tid];
            float rmax = -1e30f;
            #pragma unroll 8
            for (int j = 0; j < 64; j++) rmax = fmaxf(rmax, Ss[tid][j]);
            float mn = fmaxf(m, rmax);
            float alpha = __expf(m - mn);
            float rs = 0.f;
            #pragma unroll 8
            for (int j = 0; j < 64; j++) {
                float p = __expf(Ss[tid][j] - mn);
                Ss[tid][j] = p;
                rs += p;
            }
            lrow[tid] = lrow[tid] * alpha + rs;
            mrow[tid] = mn;
            arow[tid] = alpha;
        }
        __syncthreads();

        float al[4];
        #pragma unroll
        for (int r = 0; r < 4; r++) al[r] = arow[ty*4 + r];
        #pragma unroll
        for (int r = 0; r < 4; r++)
            #pragma unroll
            for (int c = 0; c < 4; c++) o[r][c] *= al[r];
        #pragma unroll 8
        for (int j = 0; j < 64; j++) {
            float a0 = Ss[ty*4+0][j], a1 = Ss[ty*4+1][j], a2 = Ss[ty*4+2][j], a3 = Ss[ty*4+3][j];
            float b0 = Vs[j][tx*4+0], b1 = Vs[j][tx*4+1], b2 = Vs[j][tx*4+2], b3 = Vs[j][tx*4+3];
            o[0][0] += a0*b0; o[0][1] += a0*b1; o[0][2] += a0*b2; o[0][3] += a0*b3;
            o[1][0] += a1*b0; o[1][1] += a1*b1; o[1][2] += a1*b2; o[1][3] += a1*b3;
            o[2][0] += a2*b0; o[2][1] += a2*b1; o[2][2] += a2*b2; o[2][3] += a2*b3;
            o[3][0] += a3*b0; o[3][1] += a3*b1; o[3][2] += a3*b2; o[3][3] += a3*b3;
        }
    }
    __syncthreads();

    #pragma unroll
    for (int r = 0; r < 4; r++) {
        float inv_l = 1.0f / lrow[ty*4 + r];
        #pragma unroll
        for (int c = 0; c < 4; c++) {
            O[base + (size_t)(qb*64 + ty*4 + r) * DIM + (tx*4 + c)] = o[r][c] * inv_l;
        }
    }
}

// ---------------- launch ----------------
extern "C" void kernel_launch(void* const* d_in, const int* in_sizes, int n_in,
                              void* d_out, int out_size)
{
    const float* x    = (const float*)d_in[0];
    const int*   em   = (const int*)  d_in[1];
    const float* wq   = (const float*)d_in[2];
    const float* bq   = (const float*)d_in[3];
    const float* wk   = (const float*)d_in[4];
    const float* bk   = (const float*)d_in[5];
    const float* wv   = (const float*)d_in[6];
    const float* bv   = (const float*)d_in[7];
    const float* wo   = (const float*)d_in[8];
    const float* bo   = (const float*)d_in[9];
    const float* w1   = (const float*)d_in[10];
    const float* b1   = (const float*)d_in[11];
    const float* w2   = (const float*)d_in[12];
    const float* b2   = (const float*)d_in[13];
    const float* ga   = (const float*)d_in[14];
    const float* gf   = (const float*)d_in[15];
    float* out = (float*)d_out;

    float *xn, *q, *k, *v, *att, *x1, *h;
    cudaGetSymbolAddress((void**)&xn,  g_xn);
    cudaGetSymbolAddress((void**)&q,   g_q);
    cudaGetSymbolAddress((void**)&k,   g_k);
    cudaGetSymbolAddress((void**)&v,   g_v);
    cudaGetSymbolAddress((void**)&att, g_att);
    cudaGetSymbolAddress((void**)&x1,  g_x1);
    cudaGetSymbolAddress((void**)&h,   g_h);

    // idempotent attribute sets (no static guards allowed)
    cudaFuncSetAttribute(attn_kernel, cudaFuncAttributeMaxDynamicSharedMemorySize, ATT_SMEM_BYTES);
    cudaFuncSetAttribute(gemm_tc_kernel<0,0>, cudaFuncAttributeMaxDynamicSharedMemorySize, G_SMEM_BYTES);
    cudaFuncSetAttribute(gemm_tc_kernel<0,1>, cudaFuncAttributeMaxDynamicSharedMemorySize, G_SMEM_BYTES);
    cudaFuncSetAttribute(gemm_tc_kernel<1,0>, cudaFuncAttributeMaxDynamicSharedMemorySize, G_SMEM_BYTES);

    dim3 gProj(DIM / 128, BTOK / 128);
    dim3 gFfn1(HIDDEN / 128, BTOK / 128);

    rmsnorm_kernel<<<BTOK, 256>>>(x, ga, xn);
    gemm_tc_kernel<0,0><<<gProj, 256, G_SMEM_BYTES>>>(xn, wq, bq, nullptr, q, BTOK, DIM, DIM);
    gemm_tc_kernel<0,0><<<gProj, 256, G_SMEM_BYTES>>>(xn, wk, bk, nullptr, k, BTOK, DIM, DIM);
    gemm_tc_kernel<0,0><<<gProj, 256, G_SMEM_BYTES>>>(xn, wv, bv, nullptr, v, BTOK, DIM, DIM);
    attn_kernel<<<dim3(BB*NH, SQ/64), 256, ATT_SMEM_BYTES>>>(q, k, v, em, att);
    gemm_tc_kernel<0,1><<<gProj, 256, G_SMEM_BYTES>>>(att, wo, bo, x, x1, BTOK, DIM, DIM);
    rmsnorm_kernel<<<BTOK, 256>>>(x1, gf, xn);
    gemm_tc_kernel<1,0><<<gFfn1, 256, G_SMEM_BYTES>>>(xn, w1, b1, nullptr, h, BTOK, HIDDEN, DIM);
    gemm_tc_kernel<0,1><<<gProj, 256, G_SMEM_BYTES>>>(h, w2, b2, x1, out, BTOK, DIM, HIDDEN);
}

// round 4
// speedup vs baseline: 2.4895x; 1.7307x over previous
#include <cuda_runtime.h>
#include <cuda_bf16.h>
#include <stdint.h>
#include <math.h>

#define DIM 1024
#define NH 16
#define HD 64
#define HIDDEN 4096
#define SQ 2048
#define BB 4
#define BTOK (BB*SQ)   // 8192

typedef __nv_bfloat16 bf16;
typedef __nv_bfloat162 bf162;

// ---------------- scratch: bf16 hi/lo operand buffers ----------------
__device__ bf16 g_xnH[(size_t)BTOK*DIM],  g_xnL[(size_t)BTOK*DIM];
__device__ bf16 g_qH [(size_t)BTOK*DIM],  g_qL [(size_t)BTOK*DIM];
__device__ bf16 g_kH [(size_t)BTOK*DIM],  g_kL [(size_t)BTOK*DIM];
__device__ bf16 g_vH [(size_t)BTOK*DIM],  g_vL [(size_t)BTOK*DIM];
__device__ bf16 g_attH[(size_t)BTOK*DIM], g_attL[(size_t)BTOK*DIM];
__device__ bf16 g_hH [(size_t)BTOK*HIDDEN], g_hL[(size_t)BTOK*HIDDEN];
__device__ bf16 g_wqH[(size_t)DIM*DIM],  g_wqL[(size_t)DIM*DIM];
__device__ bf16 g_wkH[(size_t)DIM*DIM],  g_wkL[(size_t)DIM*DIM];
__device__ bf16 g_wvH[(size_t)DIM*DIM],  g_wvL[(size_t)DIM*DIM];
__device__ bf16 g_woH[(size_t)DIM*DIM],  g_woL[(size_t)DIM*DIM];
__device__ bf16 g_w1H[(size_t)HIDDEN*DIM], g_w1L[(size_t)HIDDEN*DIM];
__device__ bf16 g_w2H[(size_t)DIM*HIDDEN], g_w2L[(size_t)DIM*HIDDEN];
__device__ float g_x1[(size_t)BTOK*DIM];

// ---------------- helpers ----------------
__device__ __forceinline__ uint32_t smem_u32(const void* p) {
    return (uint32_t)__cvta_generic_to_shared(p);
}
__device__ __forceinline__ void cpa16(uint32_t dst, const void* src) {
    asm volatile("cp.async.cg.shared.global [%0], [%1], 16;\n" :: "r"(dst), "l"(src));
}
#define CP_COMMIT() asm volatile("cp.async.commit_group;\n" ::)
#define CP_WAIT(n)  asm volatile("cp.async.wait_group %0;\n" :: "n"(n))

__device__ __forceinline__ void ldm_x4(uint32_t& r0, uint32_t& r1, uint32_t& r2, uint32_t& r3, uint32_t addr) {
    asm volatile("ldmatrix.sync.aligned.m8n8.x4.shared.b16 {%0,%1,%2,%3}, [%4];"
                 : "=r"(r0), "=r"(r1), "=r"(r2), "=r"(r3) : "r"(addr));
}
__device__ __forceinline__ void ldm_x2(uint32_t& r0, uint32_t& r1, uint32_t addr) {
    asm volatile("ldmatrix.sync.aligned.m8n8.x2.shared.b16 {%0,%1}, [%2];"
                 : "=r"(r0), "=r"(r1) : "r"(addr));
}
__device__ __forceinline__ void ldm_x2t(uint32_t& r0, uint32_t& r1, uint32_t addr) {
    asm volatile("ldmatrix.sync.aligned.m8n8.x2.trans.shared.b16 {%0,%1}, [%2];"
                 : "=r"(r0), "=r"(r1) : "r"(addr));
}
__device__ __forceinline__ void mma_bf16(float* c, const uint32_t* a, const uint32_t* b) {
    asm volatile("mma.sync.aligned.m16n8k16.row.col.f32.bf16.bf16.f32 "
                 "{%0,%1,%2,%3},{%4,%5,%6,%7},{%8,%9},{%0,%1,%2,%3};"
                 : "+f"(c[0]), "+f"(c[1]), "+f"(c[2]), "+f"(c[3])
                 : "r"(a[0]), "r"(a[1]), "r"(a[2]), "r"(a[3]), "r"(b[0]), "r"(b[1]));
}
__device__ __forceinline__ uint32_t pack2(float x, float y) {
    bf162 t = __float22bfloat162_rn(make_float2(x, y));
    return *(uint32_t*)&t;
}
__device__ __forceinline__ void split2(float x, float y, uint32_t& hi, uint32_t& lo) {
    bf16 hx = __float2bfloat16(x), hy = __float2bfloat16(y);
    bf162 h; h.x = hx; h.y = hy;
    hi = *(uint32_t*)&h;
    lo = pack2(x - __bfloat162float(hx), y - __bfloat162float(hy));
}

// ---------------- weight split kernel ----------------
__global__ void __launch_bounds__(256) split_kernel(const float* __restrict__ in,
                                                    bf16* __restrict__ hi, bf16* __restrict__ lo, int n4)
{
    int i = blockIdx.x * 256 + threadIdx.x;
    if (i >= n4) return;
    float4 v = ((const float4*)in)[i];
    uint32_t h0, l0, h1, l1;
    split2(v.x, v.y, h0, l0);
    split2(v.z, v.w, h1, l1);
    ((uint32_t*)hi)[i*2]   = h0; ((uint32_t*)hi)[i*2+1] = h1;
    ((uint32_t*)lo)[i*2]   = l0; ((uint32_t*)lo)[i*2+1] = l1;
}

// ---------------- RMSNorm -> bf16 hi/lo ----------------
__global__ void __launch_bounds__(256) rmsnorm_bf16_kernel(const float* __restrict__ x,
                                                           const float* __restrict__ g,
                                                           bf16* __restrict__ oh, bf16* __restrict__ ol)
{
    int row = blockIdx.x;
    int t = threadIdx.x;
    float4 xv = ((const float4*)(x + (size_t)row * DIM))[t];
    float ss = xv.x*xv.x + xv.y*xv.y + xv.z*xv.z + xv.w*xv.w;
    #pragma unroll
    for (int o = 16; o; o >>= 1) ss += __shfl_xor_sync(0xffffffffu, ss, o);
    __shared__ float sred[8];
    if ((t & 31) == 0) sred[t >> 5] = ss;
    __syncthreads();
    if (t < 8) {
        float s = sred[t];
        #pragma unroll
        for (int o = 4; o; o >>= 1) s += __shfl_xor_sync(0xffu, s, o);
        if (t == 0) sred[0] = s;
    }
    __syncthreads();
    float rr = rsqrtf(sred[0] * (1.0f / DIM) + 1e-6f);
    float4 gv = ((const float4*)g)[t];
    float v0 = xv.x*rr*gv.x, v1 = xv.y*rr*gv.y, v2 = xv.z*rr*gv.z, v3 = xv.w*rr*gv.w;
    uint32_t h0, l0, h1, l1;
    split2(v0, v1, h0, l0);
    split2(v2, v3, h1, l1);
    size_t off = ((size_t)row * DIM) / 2 + t*2;
    ((uint32_t*)oh)[off] = h0; ((uint32_t*)oh)[off+1] = h1;
    ((uint32_t*)ol)[off] = l0; ((uint32_t*)ol)[off+1] = l1;
}

// ---------------- Tensor-core GEMM, bf16 pre-split inputs, cp.async 3-stage ----------------
// C[M,N] = A @ B^T (+bias)(relu)(*oscale)(+res). 128x128 tile, BK=32, 256 thr.
#define GPAD 40
#define G_ARR_B (128*GPAD*2)            // 10240 B per array
#define G_STAGE_B (4*G_ARR_B)           // 40960
#define G_SMEM_BYTES (3*G_STAGE_B)      // 122880

__device__ __forceinline__ void gemm_issue(const bf16* AH, const bf16* AL,
                                           const bf16* BH, const bf16* BL,
                                           int K, int m0, int n0, int kb,
                                           char* slot, int tid)
{
    int row = tid >> 1;
    int cb = (tid & 1) * 16;
    size_t ao = (size_t)(m0 + row) * K + (size_t)kb * 32 + cb;
    size_t bo = (size_t)(n0 + row) * K + (size_t)kb * 32 + cb;
    uint32_t d = smem_u32(slot) + (uint32_t)(row * GPAD + cb) * 2;
    cpa16(d,                AH + ao); cpa16(d + 16,               AH + ao + 8);
    cpa16(d + G_ARR_B,      AL + ao); cpa16(d + G_ARR_B + 16,     AL + ao + 8);
    cpa16(d + 2*G_ARR_B,    BH + bo); cpa16(d + 2*G_ARR_B + 16,   BH + bo + 8);
    cpa16(d + 3*G_ARR_B,    BL + bo); cpa16(d + 3*G_ARR_B + 16,   BL + bo + 8);
}

template<int RELU, int RES, int OBF>
__global__ void __launch_bounds__(256) gemm_tc_kernel(
    const bf16* __restrict__ AH, const bf16* __restrict__ AL,
    const bf16* __restrict__ BH, const bf16* __restrict__ BL,
    const float* __restrict__ bias, const float* __restrict__ res,
    float* __restrict__ C, bf16* __restrict__ CH, bf16* __restrict__ CL,
    float oscale, int M, int N, int K)
{
    extern __shared__ char dynsm[];
    const int tid = threadIdx.x;
    const int lane = tid & 31;
    const int wid = tid >> 5;
    const int wm = wid >> 2, wn = wid & 3;
    const int m0 = blockIdx.y * 128, n0 = blockIdx.x * 128;
    const int nk = K / 32;

    float acc[4][4][4];
    #pragma unroll
    for (int i = 0; i < 4; i++)
        #pragma unroll
        for (int j = 0; j < 4; j++)
            #pragma unroll
            for (int c = 0; c < 4; c++) acc[i][j][c] = 0.f;

    gemm_issue(AH, AL, BH, BL, K, m0, n0, 0, dynsm, tid);              CP_COMMIT();
    gemm_issue(AH, AL, BH, BL, K, m0, n0, 1, dynsm + G_STAGE_B, tid);  CP_COMMIT();

    const int a_row = lane & 15;
    const int a_col = (lane >> 4) << 3;
    const int b_row = lane & 7;
    const int b_col = ((lane >> 3) & 1) << 3;

    for (int kb = 0; kb < nk; kb++) {
        if (kb + 1 < nk) { CP_WAIT(1); } else { CP_WAIT(0); }
        __syncthreads();
        if (kb + 2 < nk) {
            gemm_issue(AH, AL, BH, BL, K, m0, n0, kb + 2, dynsm + ((kb + 2) % 3) * G_STAGE_B, tid);
            CP_COMMIT();
        }
        char* slot = dynsm + (kb % 3) * G_STAGE_B;
        const uint32_t baH = smem_u32(slot);
        const uint32_t baL = baH + G_ARR_B;
        const uint32_t bbH = baH + 2*G_ARR_B;
        const uint32_t bbL = baH + 3*G_ARR_B;

        #pragma unroll
        for (int ks = 0; ks < 2; ks++) {
            const int k0 = ks * 16;
            uint32_t aH[4][4], aL[4][4], bH[4][2], bL[4][2];
            #pragma unroll
            for (int mi = 0; mi < 4; mi++) {
                uint32_t off = (uint32_t)((wm*64 + mi*16 + a_row) * GPAD + k0 + a_col) * 2;
                ldm_x4(aH[mi][0], aH[mi][1], aH[mi][2], aH[mi][3], baH + off);
                ldm_x4(aL[mi][0], aL[mi][1], aL[mi][2], aL[mi][3], baL + off);
            }
            #pragma unroll
            for (int ni = 0; ni < 4; ni++) {
                uint32_t off = (uint32_t)((wn*32 + ni*8 + b_row) * GPAD + k0 + b_col) * 2;
                ldm_x2(bH[ni][0], bH[ni][1], bbH + off);
                ldm_x2(bL[ni][0], bL[ni][1], bbL + off);
            }
            #pragma unroll
            for (int mi = 0; mi < 4; mi++)
                #pragma unroll
                for (int ni = 0; ni < 4; ni++) {
                    mma_bf16(acc[mi][ni], aH[mi], bH[ni]);
                    mma_bf16(acc[mi][ni], aH[mi], bL[ni]);
                    mma_bf16(acc[mi][ni], aL[mi], bH[ni]);
                }
        }
    }

    const int g = lane >> 2, tg = lane & 3;
    #pragma unroll
    for (int mi = 0; mi < 4; mi++) {
        const int row = m0 + wm*64 + mi*16 + g;
        #pragma unroll
        for (int ni = 0; ni < 4; ni++) {
            const int col = n0 + wn*32 + ni*8 + tg*2;
            float bv0 = bias[col], bv1 = bias[col + 1];
            float v0 = acc[mi][ni][0] + bv0, v1 = acc[mi][ni][1] + bv1;
            float v2 = acc[mi][ni][2] + bv0, v3 = acc[mi][ni][3] + bv1;
            if (RELU) { v0 = fmaxf(v0, 0.f); v1 = fmaxf(v1, 0.f); v2 = fmaxf(v2, 0.f); v3 = fmaxf(v3, 0.f); }
            if (RES) {
                const float2 r0 = *(const float2*)(res + (size_t)row * N + col);
                const float2 r1 = *(const float2*)(res + (size_t)(row + 8) * N + col);
                v0 += r0.x; v1 += r0.y; v2 += r1.x; v3 += r1.y;
            }
            v0 *= oscale; v1 *= oscale; v2 *= oscale; v3 *= oscale;
            if (OBF) {
                uint32_t h0, l0, h1, l1;
                split2(v0, v1, h0, l0);
                split2(v2, v3, h1, l1);
                *(uint32_t*)(CH + (size_t)row * N + col)       = h0;
                *(uint32_t*)(CL + (size_t)row * N + col)       = l0;
                *(uint32_t*)(CH + (size_t)(row + 8) * N + col) = h1;
                *(uint32_t*)(CL + (size_t)(row + 8) * N + col) = l1;
            } else {
                *(float2*)(C + (size_t)row * N + col)       = make_float2(v0, v1);
                *(float2*)(C + (size_t)(row + 8) * N + col) = make_float2(v2, v3);
            }
        }
    }
}

// ---------------- Tensor-core flash attention ----------------
// Br=128, Bc=64. 8 warps x 16 q-rows. Q,K,P,V all hi/lo split (3-mma).
#define APAD 72                         // bf16 row stride (144B)
#define A_Q_B   (128*APAD*2)            // 18432 per Q array
#define A_KV_B  (64*APAD*2)             // 9216 per K/V array
#define A_ST_B  (4*A_KV_B)              // 36864 per KV stage
#define A_Q_OFF 0
#define A_KV_OFF (2*A_Q_B)              // 36864
#define A_MSK_OFF (A_KV_OFF + 2*A_ST_B) // 110592
#define ATT_SMEM_BYTES (A_MSK_OFF + SQ*4)  // 118784

__device__ __forceinline__ void attn_issue_kv(const bf16* KH, const bf16* KL,
                                              const bf16* VH, const bf16* VL,
                                              size_t base, int kb, char* slot, int tid)
{
    int row = tid >> 2;
    int cb = (tid & 3) * 16;
    size_t o = base + (size_t)(kb * 64 + row) * DIM + cb;
    uint32_t d = smem_u32(slot) + (uint32_t)(row * APAD + cb) * 2;
    cpa16(d,              KH + o); cpa16(d + 16,              KH + o + 8);
    cpa16(d + A_KV_B,     KL + o); cpa16(d + A_KV_B + 16,     KL + o + 8);
    cpa16(d + 2*A_KV_B,   VH + o); cpa16(d + 2*A_KV_B + 16,   VH + o + 8);
    cpa16(d + 3*A_KV_B,   VL + o); cpa16(d + 3*A_KV_B + 16,   VL + o + 8);
}

__global__ void __launch_bounds__(256) attn_tc_kernel(
    const bf16* __restrict__ QH, const bf16* __restrict__ QL,
    const bf16* __restrict__ KH, const bf16* __restrict__ KL,
    const bf16* __restrict__ VH, const bf16* __restrict__ VL,
    const int* __restrict__ emask,
    bf16* __restrict__ OH, bf16* __restrict__ OL)
{
    extern __shared__ char sm[];
    char* qslot = sm + A_Q_OFF;
    float* smask = (float*)(sm + A_MSK_OFF);

    const int bh = blockIdx.x;            // 0..63
    const int qb = blockIdx.y;            // 0..15
    const int b = bh >> 4, h = bh & 15;
    const size_t base = (size_t)b * SQ * DIM + (size_t)h * HD;
    const int tid = threadIdx.x;
    const int lane = tid & 31;
    const int wid = tid >> 5;
    const int g = lane >> 2, tg = lane & 3;

    // Q load (rows qb*128 .. +127)
    {
        int row = tid >> 1;
        int cb = (tid & 1) * 32;
        size_t o = base + (size_t)(qb * 128 + row) * DIM + cb;
        uint32_t d = smem_u32(qslot) + (uint32_t)(row * APAD + cb) * 2;
        #pragma unroll
        for (int c = 0; c < 4; c++) {
            cpa16(d + c*16,         QH + o + c*8);
            cpa16(d + A_Q_B + c*16, QL + o + c*8);
        }
    }
    attn_issue_kv(KH, KL, VH, VL, base, 0, sm + A_KV_OFF, tid);
    CP_COMMIT();

    // mask -> float flags (0 = keep, -1 = masked)
    for (int i = tid; i < SQ; i += 256)
        smask[i] = (emask[b * SQ + i] != 0) ? 0.f : -1.f;

    CP_WAIT(0);
    __syncthreads();

    // resident Q fragments
    uint32_t qfH[4][4], qfL[4][4];
    {
        const uint32_t bqH = smem_u32(qslot);
        const uint32_t bqL = bqH + A_Q_B;
        const int a_row = lane & 15;
        const int a_col = (lane >> 4) << 3;
        #pragma unroll
        for (int kk = 0; kk < 4; kk++) {
            uint32_t off = (uint32_t)((wid*16 + a_row) * APAD + kk*16 + a_col) * 2;
            ldm_x4(qfH[kk][0], qfH[kk][1], qfH[kk][2], qfH[kk][3], bqH + off);
            ldm_x4(qfL[kk][0], qfL[kk][1], qfL[kk][2], qfL[kk][3], bqL + off);
        }
    }

    float oacc[8][4];
    #pragma unroll
    for (int d = 0; d < 8; d++)
        #pragma unroll
        for (int c = 0; c < 4; c++) oacc[d][c] = 0.f;
    float m0 = -1e30f, m1 = -1e30f, l0 = 0.f, l1 = 0.f;

    const int b_row = lane & 7;
    const int b_col = ((lane >> 3) & 1) << 3;
    const int t_row = lane & 15;

    for (int kb = 0; kb < SQ/64; kb++) {
        if (kb + 1 < SQ/64) {
            attn_issue_kv(KH, KL, VH, VL, base, kb + 1, sm + A_KV_OFF + ((kb + 1) & 1) * A_ST_B, tid);
            CP_COMMIT();
        }
        char* slot = sm + A_KV_OFF + (kb & 1) * A_ST_B;
        const uint32_t bkH = smem_u32(slot);
        const uint32_t bkL = bkH + A_KV_B;
        const uint32_t bvH = bkH + 2*A_KV_B;
        const uint32_t bvL = bkH + 3*A_KV_B;

        // S = Q K^T
        float sacc[8][4];
        #pragma unroll
        for (int nt = 0; nt < 8; nt++)
            #pragma unroll
            for (int c = 0; c < 4; c++) sacc[nt][c] = 0.f;
        #pragma unroll
        for (int kk = 0; kk < 4; kk++) {
            uint32_t kbH[8][2], kbL[8][2];
            #pragma unroll
            for (int nt = 0; nt < 8; nt++) {
                uint32_t off = (uint32_t)((nt*8 + b_row) * APAD + kk*16 + b_col) * 2;
                ldm_x2(kbH[nt][0], kbH[nt][1], bkH + off);
                ldm_x2(kbL[nt][0], kbL[nt][1], bkL + off);
            }
            #pragma unroll
            for (int nt = 0; nt < 8; nt++) {
                mma_bf16(sacc[nt], qfH[kk], kbH[nt]);
                mma_bf16(sacc[nt], qfH[kk], kbL[nt]);
                mma_bf16(sacc[nt], qfL[kk], kbH[nt]);
            }
        }

        // mask + online softmax
        float mx0 = -1e30f, mx1 = -1e30f;
        #pragma unroll
        for (int nt = 0; nt < 8; nt++) {
            int col = kb*64 + nt*8 + tg*2;
            float f0 = smask[col], f1 = smask[col + 1];
            if (f0 < 0.f) { sacc[nt][0] = -1e9f; sacc[nt][2] = -1e9f; }
            if (f1 < 0.f) { sacc[nt][1] = -1e9f; sacc[nt][3] = -1e9f; }
            mx0 = fmaxf(mx0, fmaxf(sacc[nt][0], sacc[nt][1]));
            mx1 = fmaxf(mx1, fmaxf(sacc[nt][2], sacc[nt][3]));
        }
        mx0 = fmaxf(mx0, __shfl_xor_sync(0xffffffffu, mx0, 1));
        mx0 = fmaxf(mx0, __shfl_xor_sync(0xffffffffu, mx0, 2));
        mx1 = fmaxf(mx1, __shfl_xor_sync(0xffffffffu, mx1, 1));
        mx1 = fmaxf(mx1, __shfl_xor_sync(0xffffffffu, mx1, 2));
        float mn0 = fmaxf(m0, mx0), mn1 = fmaxf(m1, mx1);
        float al0 = __expf(m0 - mn0), al1 = __expf(m1 - mn1);
        float rs0 = 0.f, rs1 = 0.f;
        #pragma unroll
        for (int nt = 0; nt < 8; nt++) {
            sacc[nt][0] = __expf(sacc[nt][0] - mn0);
            sacc[nt][1] = __expf(sacc[nt][1] - mn0);
            sacc[nt][2] = __expf(sacc[nt][2] - mn1);
            sacc[nt][3] = __expf(sacc[nt][3] - mn1);
            rs0 += sacc[nt][0] + sacc[nt][1];
            rs1 += sacc[nt][2] + sacc[nt][3];
        }
        rs0 += __shfl_xor_sync(0xffffffffu, rs0, 1);
        rs0 += __shfl_xor_sync(0xffffffffu, rs0, 2);
        rs1 += __shfl_xor_sync(0xffffffffu, rs1, 1);
        rs1 += __shfl_xor_sync(0xffffffffu, rs1, 2);
        l0 = l0 * al0 + rs0; l1 = l1 * al1 + rs1;
        m0 = mn0; m1 = mn1;
        #pragma unroll
        for (int d = 0; d < 8; d++) {
            oacc[d][0] *= al0; oacc[d][1] *= al0;
            oacc[d][2] *= al1; oacc[d][3] *= al1;
        }

        // O += P V
        #pragma unroll
        for (int kk = 0; kk < 4; kk++) {
            uint32_t pH[4], pL[4];
            split2(sacc[2*kk][0],   sacc[2*kk][1],   pH[0], pL[0]);
            split2(sacc[2*kk][2],   sacc[2*kk][3],   pH[1], pL[1]);
            split2(sacc[2*kk+1][0], sacc[2*kk+1][1], pH[2], pL[2]);
            split2(sacc[2*kk+1][2], sacc[2*kk+1][3], pH[3], pL[3]);
            uint32_t vbH[8][2], vbL[8][2];
            #pragma unroll
            for (int dt = 0; dt < 8; dt++) {
                uint32_t off = (uint32_t)((kk*16 + t_row) * APAD + dt*8) * 2;
                ldm_x2t(vbH[dt][0], vbH[dt][1], bvH + off);
                ldm_x2t(vbL[dt][0], vbL[dt][1], bvL + off);
            }
            #pragma unroll
            for (int dt = 0; dt < 8; dt++) {
                mma_bf16(oacc[dt], pH, vbH[dt]);
                mma_bf16(oacc[dt], pH, vbL[dt]);
                mma_bf16(oacc[dt], pL, vbH[dt]);
            }
        }

        if (kb + 1 < SQ/64) {
            CP_WAIT(0);
            __syncthreads();
        }
    }

    // epilogue: divide by l, split to bf16 hi/lo, write
    float il0 = 1.f / l0, il1 = 1.f / l1;
    const int r0 = qb*128 + wid*16 + g;
    const int r1 = r0 + 8;
    const size_t rowoff0 = base + (size_t)r0 * DIM;
    const size_t rowoff1 = base + (size_t)r1 * DIM;
    #pragma unroll
    for (int dt = 0; dt < 8; dt++) {
        const int col = dt*8 + tg*2;
        uint32_t h0, lo0, h1, lo1;
        split2(oacc[dt][0]*il0, oacc[dt][1]*il0, h0, lo0);
        split2(oacc[dt][2]*il1, oacc[dt][3]*il1, h1, lo1);
        *(uint32_t*)(OH + rowoff0 + col) = h0;
        *(uint32_t*)(OL + rowoff0 + col) = lo0;
        *(uint32_t*)(OH + rowoff1 + col) = h1;
        *(uint32_t*)(OL + rowoff1 + col) = lo1;
    }
}

// ---------------- launch ----------------
extern "C" void kernel_launch(void* const* d_in, const int* in_sizes, int n_in,
                              void* d_out, int out_size)
{
    const float* x  = (const float*)d_in[0];
    const int*   em = (const int*)  d_in[1];
    const float* wq = (const float*)d_in[2];
    const float* bq = (const float*)d_in[3];
    const float* wk = (const float*)d_in[4];
    const float* bk = (const float*)d_in[5];
    const float* wv = (const float*)d_in[6];
    const float* bv = (const float*)d_in[7];
    const float* wo = (const float*)d_in[8];
    const float* bo = (const float*)d_in[9];
    const float* w1 = (const float*)d_in[10];
    const float* b1 = (const float*)d_in[11];
    const float* w2 = (const float*)d_in[12];
    const float* b2 = (const float*)d_in[13];
    const float* ga = (const float*)d_in[14];
    const float* gf = (const float*)d_in[15];
    float* out = (float*)d_out;

    bf16 *xnH, *xnL, *qH, *qL, *kH, *kL, *vH, *vL, *attH, *attL, *hH, *hL;
    bf16 *wqH, *wqL, *wkH, *wkL, *wvH, *wvL, *woH, *woL, *w1H, *w1L, *w2H, *w2L;
    float *x1;
    cudaGetSymbolAddress((void**)&xnH, g_xnH);  cudaGetSymbolAddress((void**)&xnL, g_xnL);
    cudaGetSymbolAddress((void**)&qH,  g_qH);   cudaGetSymbolAddress((void**)&qL,  g_qL);
    cudaGetSymbolAddress((void**)&kH,  g_kH);   cudaGetSymbolAddress((void**)&kL,  g_kL);
    cudaGetSymbolAddress((void**)&vH,  g_vH);   cudaGetSymbolAddress((void**)&vL,  g_vL);
    cudaGetSymbolAddress((void**)&attH,g_attH); cudaGetSymbolAddress((void**)&attL,g_attL);
    cudaGetSymbolAddress((void**)&hH,  g_hH);   cudaGetSymbolAddress((void**)&hL,  g_hL);
    cudaGetSymbolAddress((void**)&wqH, g_wqH);  cudaGetSymbolAddress((void**)&wqL, g_wqL);
    cudaGetSymbolAddress((void**)&wkH, g_wkH);  cudaGetSymbolAddress((void**)&wkL, g_wkL);
    cudaGetSymbolAddress((void**)&wvH, g_wvH);  cudaGetSymbolAddress((void**)&wvL, g_wvL);
    cudaGetSymbolAddress((void**)&woH, g_woH);  cudaGetSymbolAddress((void**)&woL, g_woL);
    cudaGetSymbolAddress((void**)&w1H, g_w1H);  cudaGetSymbolAddress((void**)&w1L, g_w1L);
    cudaGetSymbolAddress((void**)&w2H, g_w2H);  cudaGetSymbolAddress((void**)&w2L, g_w2L);
    cudaGetSymbolAddress((void**)&x1,  g_x1);

    cudaFuncSetAttribute(attn_tc_kernel, cudaFuncAttributeMaxDynamicSharedMemorySize, ATT_SMEM_BYTES);
    cudaFuncSetAttribute(gemm_tc_kernel<0,0,1>, cudaFuncAttributeMaxDynamicSharedMemorySize, G_SMEM_BYTES);
    cudaFuncSetAttribute(gemm_tc_kernel<1,0,1>, cudaFuncAttributeMaxDynamicSharedMemorySize, G_SMEM_BYTES);
    cudaFuncSetAttribute(gemm_tc_kernel<0,1,0>, cudaFuncAttributeMaxDynamicSharedMemorySize, G_SMEM_BYTES);

    // weight splits
    const int n1M = DIM*DIM/4, n4M = HIDDEN*DIM/4;
    split_kernel<<<(n1M+255)/256, 256>>>(wq, wqH, wqL, n1M);
    split_kernel<<<(n1M+255)/256, 256>>>(wk, wkH, wkL, n1M);
    split_kernel<<<(n1M+255)/256, 256>>>(wv, wvH, wvL, n1M);
    split_kernel<<<(n1M+255)/256, 256>>>(wo, woH, woL, n1M);
    split_kernel<<<(n4M+255)/256, 256>>>(w1, w1H, w1L, n4M);
    split_kernel<<<(n4M+255)/256, 256>>>(w2, w2H, w2L, n4M);

    dim3 gProj(DIM/128, BTOK/128);
    dim3 gFfn1(HIDDEN/128, BTOK/128);

    rmsnorm_bf16_kernel<<<BTOK, 256>>>(x, ga, xnH, xnL);
    gemm_tc_kernel<0,0,1><<<gProj, 256, G_SMEM_BYTES>>>(xnH, xnL, wqH, wqL, bq, nullptr, nullptr, qH, qL, 0.125f, BTOK, DIM, DIM);
    gemm_tc_kernel<0,0,1><<<gProj, 256, G_SMEM_BYTES>>>(xnH, xnL, wkH, wkL, bk, nullptr, nullptr, kH, kL, 1.0f,   BTOK, DIM, DIM);
    gemm_tc_kernel<0,0,1><<<gProj, 256, G_SMEM_BYTES>>>(xnH, xnL, wvH, wvL, bv, nullptr, nullptr, vH, vL, 1.0f,   BTOK, DIM, DIM);
    attn_tc_kernel<<<dim3(BB*NH, SQ/128), 256, ATT_SMEM_BYTES>>>(qH, qL, kH, kL, vH, vL, em, attH, attL);
    gemm_tc_kernel<0,1,0><<<gProj, 256, G_SMEM_BYTES>>>(attH, attL, woH, woL, bo, x, x1, nullptr, nullptr, 1.0f, BTOK, DIM, DIM);
    rmsnorm_bf16_kernel<<<BTOK, 256>>>(x1, gf, xnH, xnL);
    gemm_tc_kernel<1,0,1><<<gFfn1, 256, G_SMEM_BYTES>>>(xnH, xnL, w1H, w1L, b1, nullptr, nullptr, hH, hL, 1.0f, BTOK, HIDDEN, DIM);
    gemm_tc_kernel<0,1,0><<<gProj, 256, G_SMEM_BYTES>>>(hH, hL, w2H, w2L, b2, x1, out, nullptr, nullptr, 1.0f, BTOK, DIM, HIDDEN);
}

// round 6
// speedup vs baseline: 3.1098x; 1.2491x over previous
#include <cuda_runtime.h>
#include <cuda_bf16.h>
#include <cuda_fp16.h>
#include <stdint.h>
#include <math.h>

#define DIM 1024
#define NH 16
#define HD 64
#define HIDDEN 4096
#define SQ 2048
#define BB 4
#define BTOK (BB*SQ)   // 8192

typedef __nv_bfloat16 bf16;
typedef __nv_bfloat162 bf162;

// ---------------- scratch ----------------
__device__ __half g_xn [(size_t)BTOK*DIM];                 // activations, single fp16
__device__ __half g_att[(size_t)BTOK*DIM];
__device__ __half g_h  [(size_t)BTOK*HIDDEN];
__device__ bf16 g_qH [(size_t)BTOK*DIM],  g_qL [(size_t)BTOK*DIM];   // attention operands bf16 hi/lo
__device__ bf16 g_kH [(size_t)BTOK*DIM],  g_kL [(size_t)BTOK*DIM];
__device__ bf16 g_vH [(size_t)BTOK*DIM],  g_vL [(size_t)BTOK*DIM];
__device__ __half g_wqH[(size_t)DIM*DIM],  g_wqL[(size_t)DIM*DIM];   // weights fp16 hi/lo
__device__ __half g_wkH[(size_t)DIM*DIM],  g_wkL[(size_t)DIM*DIM];
__device__ __half g_wvH[(size_t)DIM*DIM],  g_wvL[(size_t)DIM*DIM];
__device__ __half g_woH[(size_t)DIM*DIM],  g_woL[(size_t)DIM*DIM];
__device__ __half g_w1H[(size_t)HIDDEN*DIM], g_w1L[(size_t)HIDDEN*DIM];
__device__ __half g_w2H[(size_t)DIM*HIDDEN], g_w2L[(size_t)DIM*HIDDEN];
__device__ float g_x1[(size_t)BTOK*DIM];

// ---------------- helpers ----------------
__device__ __forceinline__ uint32_t smem_u32(const void* p) {
    return (uint32_t)__cvta_generic_to_shared(p);
}
__device__ __forceinline__ void cpa16(uint32_t dst, const void* src) {
    asm volatile("cp.async.cg.shared.global [%0], [%1], 16;\n" :: "r"(dst), "l"(src));
}
#define CP_COMMIT() asm volatile("cp.async.commit_group;\n" ::)
#define CP_WAIT(n)  asm volatile("cp.async.wait_group %0;\n" :: "n"(n))

__device__ __forceinline__ void ldm_x4(uint32_t& r0, uint32_t& r1, uint32_t& r2, uint32_t& r3, uint32_t addr) {
    asm volatile("ldmatrix.sync.aligned.m8n8.x4.shared.b16 {%0,%1,%2,%3}, [%4];"
                 : "=r"(r0), "=r"(r1), "=r"(r2), "=r"(r3) : "r"(addr));
}
__device__ __forceinline__ void ldm_x2(uint32_t& r0, uint32_t& r1, uint32_t addr) {
    asm volatile("ldmatrix.sync.aligned.m8n8.x2.shared.b16 {%0,%1}, [%2];"
                 : "=r"(r0), "=r"(r1) : "r"(addr));
}
__device__ __forceinline__ void ldm_x2t(uint32_t& r0, uint32_t& r1, uint32_t addr) {
    asm volatile("ldmatrix.sync.aligned.m8n8.x2.trans.shared.b16 {%0,%1}, [%2];"
                 : "=r"(r0), "=r"(r1) : "r"(addr));
}
__device__ __forceinline__ void mma_bf16(float* c, const uint32_t* a, const uint32_t* b) {
    asm volatile("mma.sync.aligned.m16n8k16.row.col.f32.bf16.bf16.f32 "
                 "{%0,%1,%2,%3},{%4,%5,%6,%7},{%8,%9},{%0,%1,%2,%3};"
                 : "+f"(c[0]), "+f"(c[1]), "+f"(c[2]), "+f"(c[3])
                 : "r"(a[0]), "r"(a[1]), "r"(a[2]), "r"(a[3]), "r"(b[0]), "r"(b[1]));
}
__device__ __forceinline__ void mma_f16(float* c, const uint32_t* a, const uint32_t* b) {
    asm volatile("mma.sync.aligned.m16n8k16.row.col.f32.f16.f16.f32 "
                 "{%0,%1,%2,%3},{%4,%5,%6,%7},{%8,%9},{%0,%1,%2,%3};"
                 : "+f"(c[0]), "+f"(c[1]), "+f"(c[2]), "+f"(c[3])
                 : "r"(a[0]), "r"(a[1]), "r"(a[2]), "r"(a[3]), "r"(b[0]), "r"(b[1]));
}
__device__ __forceinline__ uint32_t pack2bf(float x, float y) {
    bf162 t = __float22bfloat162_rn(make_float2(x, y));
    return *(uint32_t*)&t;
}
__device__ __forceinline__ void split2bf(float x, float y, uint32_t& hi, uint32_t& lo) {
    bf16 hx = __float2bfloat16(x), hy = __float2bfloat16(y);
    bf162 h; h.x = hx; h.y = hy;
    hi = *(uint32_t*)&h;
    lo = pack2bf(x - __bfloat162float(hx), y - __bfloat162float(hy));
}
__device__ __forceinline__ void split2h(float x, float y, uint32_t& hi, uint32_t& lo) {
    __half hx = __float2half_rn(x), hy = __float2half_rn(y);
    __half2 h; h.x = hx; h.y = hy;
    hi = *(uint32_t*)&h;
    __half2 l = __floats2half2_rn(x - __half2float(hx), y - __half2float(hy));
    lo = *(uint32_t*)&l;
}

// ---------------- weight split (fp16 hi/lo) ----------------
__global__ void __launch_bounds__(256) split_h_kernel(const float* __restrict__ in,
                                                      __half* __restrict__ hi, __half* __restrict__ lo, int n4)
{
    int i = blockIdx.x * 256 + threadIdx.x;
    if (i >= n4) return;
    float4 v = ((const float4*)in)[i];
    uint32_t h0, l0, h1, l1;
    split2h(v.x, v.y, h0, l0);
    split2h(v.z, v.w, h1, l1);
    ((uint32_t*)hi)[i*2]   = h0; ((uint32_t*)hi)[i*2+1] = h1;
    ((uint32_t*)lo)[i*2]   = l0; ((uint32_t*)lo)[i*2+1] = l1;
}

// ---------------- RMSNorm -> single fp16 ----------------
__global__ void __launch_bounds__(256) rmsnorm_h_kernel(const float* __restrict__ x,
                                                        const float* __restrict__ g,
                                                        __half* __restrict__ out)
{
    int row = blockIdx.x;
    int t = threadIdx.x;
    float4 xv = ((const float4*)(x + (size_t)row * DIM))[t];
    float ss = xv.x*xv.x + xv.y*xv.y + xv.z*xv.z + xv.w*xv.w;
    #pragma unroll
    for (int o = 16; o; o >>= 1) ss += __shfl_xor_sync(0xffffffffu, ss, o);
    __shared__ float sred[8];
    if ((t & 31) == 0) sred[t >> 5] = ss;
    __syncthreads();
    if (t < 8) {
        float s = sred[t];
        #pragma unroll
        for (int o = 4; o; o >>= 1) s += __shfl_xor_sync(0xffu, s, o);
        if (t == 0) sred[0] = s;
    }
    __syncthreads();
    float rr = rsqrtf(sred[0] * (1.0f / DIM) + 1e-6f);
    float4 gv = ((const float4*)g)[t];
    __half2 h0 = __floats2half2_rn(xv.x*rr*gv.x, xv.y*rr*gv.y);
    __half2 h1 = __floats2half2_rn(xv.z*rr*gv.z, xv.w*rr*gv.w);
    size_t off = ((size_t)row * DIM) / 2 + t*2;
    ((__half2*)out)[off]   = h0;
    ((__half2*)out)[off+1] = h1;
}

// ---------------- fp16 tensor-core GEMM (A single, B hi/lo, 2 mma/k16) ----------------
// C[M,N] = A @ B^T (+bias)(relu)(*oscale)(+res). 128x128 tile, BK=32, 4-stage cp.async.
// OMODE: 0 -> fp32 C, 1 -> bf16 hi/lo (CH,CL), 2 -> fp16 single (CF)
#define GPAD 40
#define T_ARR_B (128*GPAD*2)            // 10240 B
#define T_STAGE_B (3*T_ARR_B)           // A, BH, BL = 30720
#define G_SMEM_BYTES (4*T_STAGE_B)      // 122880

__device__ __forceinline__ void tgemm_issue(const __half* A, const __half* BH, const __half* BL,
                                            int K, int m0, int n0, int kb,
                                            uint32_t slot, int tid)
{
    int row = tid >> 1;
    int cb = (tid & 1) * 16;
    size_t ao = (size_t)(m0 + row) * K + (size_t)kb * 32 + cb;
    size_t bo = (size_t)(n0 + row) * K + (size_t)kb * 32 + cb;
    uint32_t d = slot + (uint32_t)(row * GPAD + cb) * 2;
    cpa16(d,                A  + ao); cpa16(d + 16,               A  + ao + 8);
    cpa16(d + T_ARR_B,      BH + bo); cpa16(d + T_ARR_B + 16,     BH + bo + 8);
    cpa16(d + 2*T_ARR_B,    BL + bo); cpa16(d + 2*T_ARR_B + 16,   BL + bo + 8);
}

template<int RELU, int RES, int OMODE>
__global__ void __launch_bounds__(256) gemm_h_kernel(
    const __half* __restrict__ A,
    const __half* __restrict__ BH, const __half* __restrict__ BL,
    const float* __restrict__ bias, const float* __restrict__ res,
    float* __restrict__ C, bf16* __restrict__ CH, bf16* __restrict__ CL,
    __half* __restrict__ CF,
    float oscale, int M, int N, int K)
{
    extern __shared__ char dynsm[];
    const uint32_t smb = smem_u32(dynsm);
    const int tid = threadIdx.x;
    const int lane = tid & 31;
    const int wid = tid >> 5;
    const int wm = wid >> 2, wn = wid & 3;
    const int m0 = blockIdx.y * 128, n0 = blockIdx.x * 128;
    const int nk = K / 32;

    float acc[4][4][4];
    #pragma unroll
    for (int i = 0; i < 4; i++)
        #pragma unroll
        for (int j = 0; j < 4; j++)
            #pragma unroll
            for (int c = 0; c < 4; c++) acc[i][j][c] = 0.f;

    tgemm_issue(A, BH, BL, K, m0, n0, 0, smb,               tid); CP_COMMIT();
    tgemm_issue(A, BH, BL, K, m0, n0, 1, smb + T_STAGE_B,   tid); CP_COMMIT();
    tgemm_issue(A, BH, BL, K, m0, n0, 2, smb + 2*T_STAGE_B, tid); CP_COMMIT();

    const int a_row = lane & 15;
    const int a_col = (lane >> 4) << 3;
    const int b_row = lane & 7;
    const int b_col = ((lane >> 3) & 1) << 3;

    for (int kb = 0; kb < nk; kb++) {
        if (kb < nk - 2)      { CP_WAIT(2); }
        else if (kb == nk - 2){ CP_WAIT(1); }
        else                  { CP_WAIT(0); }
        __syncthreads();
        if (kb + 3 < nk) {
            tgemm_issue(A, BH, BL, K, m0, n0, kb + 3, smb + ((kb + 3) & 3) * T_STAGE_B, tid);
            CP_COMMIT();
        }
        const uint32_t sb = smb + (kb & 3) * T_STAGE_B;
        const uint32_t baA = sb;
        const uint32_t bbH = sb + T_ARR_B;
        const uint32_t bbL = sb + 2*T_ARR_B;

        #pragma unroll
        for (int ks = 0; ks < 2; ks++) {
            const int k0 = ks * 16;
            uint32_t aF[4][4], bH[4][2], bL[4][2];
            #pragma unroll
            for (int mi = 0; mi < 4; mi++) {
                uint32_t off = (uint32_t)((wm*64 + mi*16 + a_row) * GPAD + k0 + a_col) * 2;
                ldm_x4(aF[mi][0], aF[mi][1], aF[mi][2], aF[mi][3], baA + off);
            }
            #pragma unroll
            for (int ni = 0; ni < 4; ni++) {
                uint32_t off = (uint32_t)((wn*32 + ni*8 + b_row) * GPAD + k0 + b_col) * 2;
                ldm_x2(bH[ni][0], bH[ni][1], bbH + off);
                ldm_x2(bL[ni][0], bL[ni][1], bbL + off);
            }
            #pragma unroll
            for (int mi = 0; mi < 4; mi++)
                #pragma unroll
                for (int ni = 0; ni < 4; ni++) {
                    mma_f16(acc[mi][ni], aF[mi], bH[ni]);
                    mma_f16(acc[mi][ni], aF[mi], bL[ni]);
                }
        }
    }

    const int g = lane >> 2, tg = lane & 3;
    #pragma unroll
    for (int mi = 0; mi < 4; mi++) {
        const int row = m0 + wm*64 + mi*16 + g;
        #pragma unroll
        for (int ni = 0; ni < 4; ni++) {
            const int col = n0 + wn*32 + ni*8 + tg*2;
            float bv0 = bias[col], bv1 = bias[col + 1];
            float v0 = acc[mi][ni][0] + bv0, v1 = acc[mi][ni][1] + bv1;
            float v2 = acc[mi][ni][2] + bv0, v3 = acc[mi][ni][3] + bv1;
            if (RELU) { v0 = fmaxf(v0, 0.f); v1 = fmaxf(v1, 0.f); v2 = fmaxf(v2, 0.f); v3 = fmaxf(v3, 0.f); }
            if (RES) {
                const float2 r0 = *(const float2*)(res + (size_t)row * N + col);
                const float2 r1 = *(const float2*)(res + (size_t)(row + 8) * N + col);
                v0 += r0.x; v1 += r0.y; v2 += r1.x; v3 += r1.y;
            }
            v0 *= oscale; v1 *= oscale; v2 *= oscale; v3 *= oscale;
            if (OMODE == 1) {
                uint32_t h0, l0, h1, l1;
                split2bf(v0, v1, h0, l0);
                split2bf(v2, v3, h1, l1);
                *(uint32_t*)(CH + (size_t)row * N + col)       = h0;
                *(uint32_t*)(CL + (size_t)row * N + col)       = l0;
                *(uint32_t*)(CH + (size_t)(row + 8) * N + col) = h1;
                *(uint32_t*)(CL + (size_t)(row + 8) * N + col) = l1;
            } else if (OMODE == 2) {
                *(__half2*)(CF + (size_t)row * N + col)       = __floats2half2_rn(v0, v1);
                *(__half2*)(CF + (size_t)(row + 8) * N + col) = __floats2half2_rn(v2, v3);
            } else {
                *(float2*)(C + (size_t)row * N + col)       = make_float2(v0, v1);
                *(float2*)(C + (size_t)(row + 8) * N + col) = make_float2(v2, v3);
            }
        }
    }
}

// ---------------- Tensor-core flash attention (verified R4; fp16 output) ----------------
#define APAD 72
#define A_Q_B   (128*APAD*2)
#define A_KV_B  (64*APAD*2)
#define A_ST_B  (4*A_KV_B)
#define A_Q_OFF 0
#define A_KV_OFF (2*A_Q_B)
#define A_MSK_OFF (A_KV_OFF + 2*A_ST_B)
#define ATT_SMEM_BYTES (A_MSK_OFF + SQ*4)

__device__ __forceinline__ void attn_issue_kv(const bf16* KH, const bf16* KL,
                                              const bf16* VH, const bf16* VL,
                                              size_t base, int kb, char* slot, int tid)
{
    int row = tid >> 2;
    int cb = (tid & 3) * 16;
    size_t o = base + (size_t)(kb * 64 + row) * DIM + cb;
    uint32_t d = smem_u32(slot) + (uint32_t)(row * APAD + cb) * 2;
    cpa16(d,              KH + o); cpa16(d + 16,              KH + o + 8);
    cpa16(d + A_KV_B,     KL + o); cpa16(d + A_KV_B + 16,     KL + o + 8);
    cpa16(d + 2*A_KV_B,   VH + o); cpa16(d + 2*A_KV_B + 16,   VH + o + 8);
    cpa16(d + 3*A_KV_B,   VL + o); cpa16(d + 3*A_KV_B + 16,   VL + o + 8);
}

__global__ void __launch_bounds__(256) attn_tc_kernel(
    const bf16* __restrict__ QH, const bf16* __restrict__ QL,
    const bf16* __restrict__ KH, const bf16* __restrict__ KL,
    const bf16* __restrict__ VH, const bf16* __restrict__ VL,
    const int* __restrict__ emask,
    __half* __restrict__ O)
{
    extern __shared__ char sm[];
    char* qslot = sm + A_Q_OFF;
    float* smask = (float*)(sm + A_MSK_OFF);

    const int bh = blockIdx.x;
    const int qb = blockIdx.y;
    const int b = bh >> 4, h = bh & 15;
    const size_t base = (size_t)b * SQ * DIM + (size_t)h * HD;
    const int tid = threadIdx.x;
    const int lane = tid & 31;
    const int wid = tid >> 5;
    const int g = lane >> 2, tg = lane & 3;

    {
        int row = tid >> 1;
        int cb = (tid & 1) * 32;
        size_t o = base + (size_t)(qb * 128 + row) * DIM + cb;
        uint32_t d = smem_u32(qslot) + (uint32_t)(row * APAD + cb) * 2;
        #pragma unroll
        for (int c = 0; c < 4; c++) {
            cpa16(d + c*16,         QH + o + c*8);
            cpa16(d + A_Q_B + c*16, QL + o + c*8);
        }
    }
    attn_issue_kv(KH, KL, VH, VL, base, 0, sm + A_KV_OFF, tid);
    CP_COMMIT();

    for (int i = tid; i < SQ; i += 256)
        smask[i] = (emask[b * SQ + i] != 0) ? 0.f : -1.f;

    CP_WAIT(0);
    __syncthreads();

    uint32_t qfH[4][4], qfL[4][4];
    {
        const uint32_t bqH = smem_u32(qslot);
        const uint32_t bqL = bqH + A_Q_B;
        const int a_row = lane & 15;
        const int a_col = (lane >> 4) << 3;
        #pragma unroll
        for (int kk = 0; kk < 4; kk++) {
            uint32_t off = (uint32_t)((wid*16 + a_row) * APAD + kk*16 + a_col) * 2;
            ldm_x4(qfH[kk][0], qfH[kk][1], qfH[kk][2], qfH[kk][3], bqH + off);
            ldm_x4(qfL[kk][0], qfL[kk][1], qfL[kk][2], qfL[kk][3], bqL + off);
        }
    }

    float oacc[8][4];
    #pragma unroll
    for (int d = 0; d < 8; d++)
        #pragma unroll
        for (int c = 0; c < 4; c++) oacc[d][c] = 0.f;
    float m0 = -1e30f, m1 = -1e30f, l0 = 0.f, l1 = 0.f;

    const int b_row = lane & 7;
    const int b_col = ((lane >> 3) & 1) << 3;
    const int t_row = lane & 15;

    for (int kb = 0; kb < SQ/64; kb++) {
        if (kb + 1 < SQ/64) {
            attn_issue_kv(KH, KL, VH, VL, base, kb + 1, sm + A_KV_OFF + ((kb + 1) & 1) * A_ST_B, tid);
            CP_COMMIT();
        }
        char* slot = sm + A_KV_OFF + (kb & 1) * A_ST_B;
        const uint32_t bkH = smem_u32(slot);
        const uint32_t bkL = bkH + A_KV_B;
        const uint32_t bvH = bkH + 2*A_KV_B;
        const uint32_t bvL = bkH + 3*A_KV_B;

        float sacc[8][4];
        #pragma unroll
        for (int nt = 0; nt < 8; nt++)
            #pragma unroll
            for (int c = 0; c < 4; c++) sacc[nt][c] = 0.f;
        #pragma unroll
        for (int kk = 0; kk < 4; kk++) {
            uint32_t kbH[8][2], kbL[8][2];
            #pragma unroll
            for (int nt = 0; nt < 8; nt++) {
                uint32_t off = (uint32_t)((nt*8 + b_row) * APAD + kk*16 + b_col) * 2;
                ldm_x2(kbH[nt][0], kbH[nt][1], bkH + off);
                ldm_x2(kbL[nt][0], kbL[nt][1], bkL + off);
            }
            #pragma unroll
            for (int nt = 0; nt < 8; nt++) {
                mma_bf16(sacc[nt], qfH[kk], kbH[nt]);
                mma_bf16(sacc[nt], qfH[kk], kbL[nt]);
                mma_bf16(sacc[nt], qfL[kk], kbH[nt]);
            }
        }

        float mx0 = -1e30f, mx1 = -1e30f;
        #pragma unroll
        for (int nt = 0; nt < 8; nt++) {
            int col = kb*64 + nt*8 + tg*2;
            float f0 = smask[col], f1 = smask[col + 1];
            if (f0 < 0.f) { sacc[nt][0] = -1e9f; sacc[nt][2] = -1e9f; }
            if (f1 < 0.f) { sacc[nt][1] = -1e9f; sacc[nt][3] = -1e9f; }
            mx0 = fmaxf(mx0, fmaxf(sacc[nt][0], sacc[nt][1]));
            mx1 = fmaxf(mx1, fmaxf(sacc[nt][2], sacc[nt][3]));
        }
        mx0 = fmaxf(mx0, __shfl_xor_sync(0xffffffffu, mx0, 1));
        mx0 = fmaxf(mx0, __shfl_xor_sync(0xffffffffu, mx0, 2));
        mx1 = fmaxf(mx1, __shfl_xor_sync(0xffffffffu, mx1, 1));
        mx1 = fmaxf(mx1, __shfl_xor_sync(0xffffffffu, mx1, 2));
        float mn0 = fmaxf(m0, mx0), mn1 = fmaxf(m1, mx1);
        float al0 = __expf(m0 - mn0), al1 = __expf(m1 - mn1);
        float rs0 = 0.f, rs1 = 0.f;
        #pragma unroll
        for (int nt = 0; nt < 8; nt++) {
            sacc[nt][0] = __expf(sacc[nt][0] - mn0);
            sacc[nt][1] = __expf(sacc[nt][1] - mn0);
            sacc[nt][2] = __expf(sacc[nt][2] - mn1);
            sacc[nt][3] = __expf(sacc[nt][3] - mn1);
            rs0 += sacc[nt][0] + sacc[nt][1];
            rs1 += sacc[nt][2] + sacc[nt][3];
        }
        rs0 += __shfl_xor_sync(0xffffffffu, rs0, 1);
        rs0 += __shfl_xor_sync(0xffffffffu, rs0, 2);
        rs1 += __shfl_xor_sync(0xffffffffu, rs1, 1);
        rs1 += __shfl_xor_sync(0xffffffffu, rs1, 2);
        l0 = l0 * al0 + rs0; l1 = l1 * al1 + rs1;
        m0 = mn0; m1 = mn1;
        #pragma unroll
        for (int d = 0; d < 8; d++) {
            oacc[d][0] *= al0; oacc[d][1] *= al0;
            oacc[d][2] *= al1; oacc[d][3] *= al1;
        }

        #pragma unroll
        for (int kk = 0; kk < 4; kk++) {
            uint32_t pH[4], pL[4];
            split2bf(sacc[2*kk][0],   sacc[2*kk][1],   pH[0], pL[0]);
            split2bf(sacc[2*kk][2],   sacc[2*kk][3],   pH[1], pL[1]);
            split2bf(sacc[2*kk+1][0], sacc[2*kk+1][1], pH[2], pL[2]);
            split2bf(sacc[2*kk+1][2], sacc[2*kk+1][3], pH[3], pL[3]);
            uint32_t vbH[8][2], vbL[8][2];
            #pragma unroll
            for (int dt = 0; dt < 8; dt++) {
                uint32_t off = (uint32_t)((kk*16 + t_row) * APAD + dt*8) * 2;
                ldm_x2t(vbH[dt][0], vbH[dt][1], bvH + off);
                ldm_x2t(vbL[dt][0], vbL[dt][1], bvL + off);
            }
            #pragma unroll
            for (int dt = 0; dt < 8; dt++) {
                mma_bf16(oacc[dt], pH, vbH[dt]);
                mma_bf16(oacc[dt], pH, vbL[dt]);
                mma_bf16(oacc[dt], pL, vbH[dt]);
            }
        }

        if (kb + 1 < SQ/64) {
            CP_WAIT(0);
            __syncthreads();
        }
    }

    float il0 = 1.f / l0, il1 = 1.f / l1;
    const int r0 = qb*128 + wid*16 + g;
    const int r1 = r0 + 8;
    const size_t rowoff0 = base + (size_t)r0 * DIM;
    const size_t rowoff1 = base + (size_t)r1 * DIM;
    #pragma unroll
    for (int dt = 0; dt < 8; dt++) {
        const int col = dt*8 + tg*2;
        *(__half2*)(O + rowoff0 + col) = __floats2half2_rn(oacc[dt][0]*il0, oacc[dt][1]*il0);
        *(__half2*)(O + rowoff1 + col) = __floats2half2_rn(oacc[dt][2]*il1, oacc[dt][3]*il1);
    }
}

// ---------------- launch ----------------
extern "C" void kernel_launch(void* const* d_in, const int* in_sizes, int n_in,
                              void* d_out, int out_size)
{
    const float* x  = (const float*)d_in[0];
    const int*   em = (const int*)  d_in[1];
    const float* wq = (const float*)d_in[2];
    const float* bq = (const float*)d_in[3];
    const float* wk = (const float*)d_in[4];
    const float* bk = (const float*)d_in[5];
    const float* wv = (const float*)d_in[6];
    const float* bv = (const float*)d_in[7];
    const float* wo = (const float*)d_in[8];
    const float* bo = (const float*)d_in[9];
    const float* w1 = (const float*)d_in[10];
    const float* b1 = (const float*)d_in[11];
    const float* w2 = (const float*)d_in[12];
    const float* b2 = (const float*)d_in[13];
    const float* ga = (const float*)d_in[14];
    const float* gf = (const float*)d_in[15];
    float* out = (float*)d_out;

    __half *xn, *att, *h;
    bf16 *qH, *qL, *kH, *kL, *vH, *vL;
    __half *wqH, *wqL, *wkH, *wkL, *wvH, *wvL, *woH, *woL, *w1H, *w1L, *w2H, *w2L;
    float *x1;
    cudaGetSymbolAddress((void**)&xn,  g_xn);
    cudaGetSymbolAddress((void**)&att, g_att);
    cudaGetSymbolAddress((void**)&h,   g_h);
    cudaGetSymbolAddress((void**)&qH,  g_qH);   cudaGetSymbolAddress((void**)&qL,  g_qL);
    cudaGetSymbolAddress((void**)&kH,  g_kH);   cudaGetSymbolAddress((void**)&kL,  g_kL);
    cudaGetSymbolAddress((void**)&vH,  g_vH);   cudaGetSymbolAddress((void**)&vL,  g_vL);
    cudaGetSymbolAddress((void**)&wqH, g_wqH);  cudaGetSymbolAddress((void**)&wqL, g_wqL);
    cudaGetSymbolAddress((void**)&wkH, g_wkH);  cudaGetSymbolAddress((void**)&wkL, g_wkL);
    cudaGetSymbolAddress((void**)&wvH, g_wvH);  cudaGetSymbolAddress((void**)&wvL, g_wvL);
    cudaGetSymbolAddress((void**)&woH, g_woH);  cudaGetSymbolAddress((void**)&woL, g_woL);
    cudaGetSymbolAddress((void**)&w1H, g_w1H);  cudaGetSymbolAddress((void**)&w1L, g_w1L);
    cudaGetSymbolAddress((void**)&w2H, g_w2H);  cudaGetSymbolAddress((void**)&w2L, g_w2L);
    cudaGetSymbolAddress((void**)&x1,  g_x1);

    cudaFuncSetAttribute(attn_tc_kernel, cudaFuncAttributeMaxDynamicSharedMemorySize, ATT_SMEM_BYTES);
    cudaFuncSetAttribute(gemm_h_kernel<0,0,1>, cudaFuncAttributeMaxDynamicSharedMemorySize, G_SMEM_BYTES);
    cudaFuncSetAttribute(gemm_h_kernel<1,0,2>, cudaFuncAttributeMaxDynamicSharedMemorySize, G_SMEM_BYTES);
    cudaFuncSetAttribute(gemm_h_kernel<0,1,0>, cudaFuncAttributeMaxDynamicSharedMemorySize, G_SMEM_BYTES);

    const int n1M = DIM*DIM/4, n4M = HIDDEN*DIM/4;
    split_h_kernel<<<(n1M+255)/256, 256>>>(wq, wqH, wqL, n1M);
    split_h_kernel<<<(n1M+255)/256, 256>>>(wk, wkH, wkL, n1M);
    split_h_kernel<<<(n1M+255)/256, 256>>>(wv, wvH, wvL, n1M);
    split_h_kernel<<<(n1M+255)/256, 256>>>(wo, woH, woL, n1M);
    split_h_kernel<<<(n4M+255)/256, 256>>>(w1, w1H, w1L, n4M);
    split_h_kernel<<<(n4M+255)/256, 256>>>(w2, w2H, w2L, n4M);

    dim3 gProj(DIM/128, BTOK/128);
    dim3 gFfn1(HIDDEN/128, BTOK/128);

    rmsnorm_h_kernel<<<BTOK, 256>>>(x, ga, xn);
    gemm_h_kernel<0,0,1><<<gProj, 256, G_SMEM_BYTES>>>(xn, wqH, wqL, bq, nullptr, nullptr, qH, qL, nullptr, 0.125f, BTOK, DIM, DIM);
    gemm_h_kernel<0,0,1><<<gProj, 256, G_SMEM_BYTES>>>(xn, wkH, wkL, bk, nullptr, nullptr, kH, kL, nullptr, 1.0f,   BTOK, DIM, DIM);
    gemm_h_kernel<0,0,1><<<gProj, 256, G_SMEM_BYTES>>>(xn, wvH, wvL, bv, nullptr, nullptr, vH, vL, nullptr, 1.0f,   BTOK, DIM, DIM);
    attn_tc_kernel<<<dim3(BB*NH, SQ/128), 256, ATT_SMEM_BYTES>>>(qH, qL, kH, kL, vH, vL, em, att);
    gemm_h_kernel<0,1,0><<<gProj, 256, G_SMEM_BYTES>>>(att, woH, woL, bo, x, x1, nullptr, nullptr, nullptr, 1.0f, BTOK, DIM, DIM);
    rmsnorm_h_kernel<<<BTOK, 256>>>(x1, gf, xn);
    gemm_h_kernel<1,0,2><<<gFfn1, 256, G_SMEM_BYTES>>>(xn, w1H, w1L, b1, nullptr, nullptr, nullptr, nullptr, h, 1.0f, BTOK, HIDDEN, DIM);
    gemm_h_kernel<0,1,0><<<gProj, 256, G_SMEM_BYTES>>>(h, w2H, w2L, b2, x1, out, nullptr, nullptr, nullptr, 1.0f, BTOK, DIM, HIDDEN);
}

// round 7
// speedup vs baseline: 3.7857x; 1.2173x over previous
#include <cuda_runtime.h>
#include <cuda_fp16.h>
#include <stdint.h>
#include <math.h>

#define DIM 1024
#define NH 16
#define HD 64
#define HIDDEN 4096
#define SQ 2048
#define BB 4
#define BTOK (BB*SQ)   // 8192

// ---------------- scratch ----------------
__device__ __half g_xn [(size_t)BTOK*DIM];
__device__ __half g_att[(size_t)BTOK*DIM];
__device__ __half g_h  [(size_t)BTOK*HIDDEN];
__device__ __half g_q  [(size_t)BTOK*DIM];
__device__ __half g_k  [(size_t)BTOK*DIM];
__device__ __half g_v  [(size_t)BTOK*DIM];
__device__ __half g_wqH[(size_t)DIM*DIM],  g_wqL[(size_t)DIM*DIM];
__device__ __half g_wkH[(size_t)DIM*DIM],  g_wkL[(size_t)DIM*DIM];
__device__ __half g_wvH[(size_t)DIM*DIM],  g_wvL[(size_t)DIM*DIM];
__device__ __half g_woH[(size_t)DIM*DIM],  g_woL[(size_t)DIM*DIM];
__device__ __half g_w1H[(size_t)HIDDEN*DIM], g_w1L[(size_t)HIDDEN*DIM];
__device__ __half g_w2H[(size_t)DIM*HIDDEN], g_w2L[(size_t)DIM*HIDDEN];
__device__ float g_x1[(size_t)BTOK*DIM];

// ---------------- helpers ----------------
__device__ __forceinline__ uint32_t smem_u32(const void* p) {
    return (uint32_t)__cvta_generic_to_shared(p);
}
__device__ __forceinline__ void cpa16(uint32_t dst, const void* src) {
    asm volatile("cp.async.cg.shared.global [%0], [%1], 16;\n" :: "r"(dst), "l"(src));
}
#define CP_COMMIT() asm volatile("cp.async.commit_group;\n" ::)
#define CP_WAIT(n)  asm volatile("cp.async.wait_group %0;\n" :: "n"(n))

__device__ __forceinline__ void ldm_x4(uint32_t& r0, uint32_t& r1, uint32_t& r2, uint32_t& r3, uint32_t addr) {
    asm volatile("ldmatrix.sync.aligned.m8n8.x4.shared.b16 {%0,%1,%2,%3}, [%4];"
                 : "=r"(r0), "=r"(r1), "=r"(r2), "=r"(r3) : "r"(addr));
}
__device__ __forceinline__ void ldm_x2(uint32_t& r0, uint32_t& r1, uint32_t addr) {
    asm volatile("ldmatrix.sync.aligned.m8n8.x2.shared.b16 {%0,%1}, [%2];"
                 : "=r"(r0), "=r"(r1) : "r"(addr));
}
__device__ __forceinline__ void ldm_x2t(uint32_t& r0, uint32_t& r1, uint32_t addr) {
    asm volatile("ldmatrix.sync.aligned.m8n8.x2.trans.shared.b16 {%0,%1}, [%2];"
                 : "=r"(r0), "=r"(r1) : "r"(addr));
}
__device__ __forceinline__ void mma_f16(float* c, const uint32_t* a, const uint32_t* b) {
    asm volatile("mma.sync.aligned.m16n8k16.row.col.f32.f16.f16.f32 "
                 "{%0,%1,%2,%3},{%4,%5,%6,%7},{%8,%9},{%0,%1,%2,%3};"
                 : "+f"(c[0]), "+f"(c[1]), "+f"(c[2]), "+f"(c[3])
                 : "r"(a[0]), "r"(a[1]), "r"(a[2]), "r"(a[3]), "r"(b[0]), "r"(b[1]));
}
__device__ __forceinline__ uint32_t pack2h(float x, float y) {
    __half2 t = __floats2half2_rn(x, y);
    return *(uint32_t*)&t;
}
__device__ __forceinline__ void split2h(float x, float y, uint32_t& hi, uint32_t& lo) {
    __half hx = __float2half_rn(x), hy = __float2half_rn(y);
    __half2 h; h.x = hx; h.y = hy;
    hi = *(uint32_t*)&h;
    lo = pack2h(x - __half2float(hx), y - __half2float(hy));
}

// ---------------- weight split (fp16 hi/lo) ----------------
__global__ void __launch_bounds__(256) split_h_kernel(const float* __restrict__ in,
                                                      __half* __restrict__ hi, __half* __restrict__ lo, int n4)
{
    int i = blockIdx.x * 256 + threadIdx.x;
    if (i >= n4) return;
    float4 v = ((const float4*)in)[i];
    uint32_t h0, l0, h1, l1;
    split2h(v.x, v.y, h0, l0);
    split2h(v.z, v.w, h1, l1);
    ((uint32_t*)hi)[i*2]   = h0; ((uint32_t*)hi)[i*2+1] = h1;
    ((uint32_t*)lo)[i*2]   = l0; ((uint32_t*)lo)[i*2+1] = l1;
}

// ---------------- RMSNorm -> single fp16 ----------------
__global__ void __launch_bounds__(256) rmsnorm_h_kernel(const float* __restrict__ x,
                                                        const float* __restrict__ g,
                                                        __half* __restrict__ out)
{
    int row = blockIdx.x;
    int t = threadIdx.x;
    float4 xv = ((const float4*)(x + (size_t)row * DIM))[t];
    float ss = xv.x*xv.x + xv.y*xv.y + xv.z*xv.z + xv.w*xv.w;
    #pragma unroll
    for (int o = 16; o; o >>= 1) ss += __shfl_xor_sync(0xffffffffu, ss, o);
    __shared__ float sred[8];
    if ((t & 31) == 0) sred[t >> 5] = ss;
    __syncthreads();
    if (t < 8) {
        float s = sred[t];
        #pragma unroll
        for (int o = 4; o; o >>= 1) s += __shfl_xor_sync(0xffu, s, o);
        if (t == 0) sred[0] = s;
    }
    __syncthreads();
    float rr = rsqrtf(sred[0] * (1.0f / DIM) + 1e-6f);
    float4 gv = ((const float4*)g)[t];
    __half2 h0 = __floats2half2_rn(xv.x*rr*gv.x, xv.y*rr*gv.y);
    __half2 h1 = __floats2half2_rn(xv.z*rr*gv.z, xv.w*rr*gv.w);
    size_t off = ((size_t)row * DIM) / 2 + t*2;
    ((__half2*)out)[off]   = h0;
    ((__half2*)out)[off+1] = h1;
}

// ---------------- fp16 tensor-core GEMM (A single, B hi/lo, 2 mma/k16) ----------------
// OMODE: 0 -> fp32 C, 2 -> fp16 single (CF)
#define GPAD 40
#define T_ARR_B (128*GPAD*2)
#define T_STAGE_B (3*T_ARR_B)
#define G_SMEM_BYTES (4*T_STAGE_B)      // 122880

__device__ __forceinline__ void tgemm_issue(const __half* A, const __half* BH, const __half* BL,
                                            int K, int m0, int n0, int kb,
                                            uint32_t slot, int tid)
{
    int row = tid >> 1;
    int cb = (tid & 1) * 16;
    size_t ao = (size_t)(m0 + row) * K + (size_t)kb * 32 + cb;
    size_t bo = (size_t)(n0 + row) * K + (size_t)kb * 32 + cb;
    uint32_t d = slot + (uint32_t)(row * GPAD + cb) * 2;
    cpa16(d,                A  + ao); cpa16(d + 16,               A  + ao + 8);
    cpa16(d + T_ARR_B,      BH + bo); cpa16(d + T_ARR_B + 16,     BH + bo + 8);
    cpa16(d + 2*T_ARR_B,    BL + bo); cpa16(d + 2*T_ARR_B + 16,   BL + bo + 8);
}

template<int RELU, int RES, int OMODE>
__global__ void __launch_bounds__(256) gemm_h_kernel(
    const __half* __restrict__ A,
    const __half* __restrict__ BH, const __half* __restrict__ BL,
    const float* __restrict__ bias, const float* __restrict__ res,
    float* __restrict__ C, __half* __restrict__ CF,
    float oscale, int M, int N, int K)
{
    extern __shared__ char dynsm[];
    const uint32_t smb = smem_u32(dynsm);
    const int tid = threadIdx.x;
    const int lane = tid & 31;
    const int wid = tid >> 5;
    const int wm = wid >> 2, wn = wid & 3;
    const int m0 = blockIdx.y * 128, n0 = blockIdx.x * 128;
    const int nk = K / 32;

    float acc[4][4][4];
    #pragma unroll
    for (int i = 0; i < 4; i++)
        #pragma unroll
        for (int j = 0; j < 4; j++)
            #pragma unroll
            for (int c = 0; c < 4; c++) acc[i][j][c] = 0.f;

    tgemm_issue(A, BH, BL, K, m0, n0, 0, smb,               tid); CP_COMMIT();
    tgemm_issue(A, BH, BL, K, m0, n0, 1, smb + T_STAGE_B,   tid); CP_COMMIT();
    tgemm_issue(A, BH, BL, K, m0, n0, 2, smb + 2*T_STAGE_B, tid); CP_COMMIT();

    const int a_row = lane & 15;
    const int a_col = (lane >> 4) << 3;
    const int b_row = lane & 7;
    const int b_col = ((lane >> 3) & 1) << 3;

    for (int kb = 0; kb < nk; kb++) {
        if (kb < nk - 2)      { CP_WAIT(2); }
        else if (kb == nk - 2){ CP_WAIT(1); }
        else                  { CP_WAIT(0); }
        __syncthreads();
        if (kb + 3 < nk) {
            tgemm_issue(A, BH, BL, K, m0, n0, kb + 3, smb + ((kb + 3) & 3) * T_STAGE_B, tid);
            CP_COMMIT();
        }
        const uint32_t sb = smb + (kb & 3) * T_STAGE_B;
        const uint32_t baA = sb;
        const uint32_t bbH = sb + T_ARR_B;
        const uint32_t bbL = sb + 2*T_ARR_B;

        #pragma unroll
        for (int ks = 0; ks < 2; ks++) {
            const int k0 = ks * 16;
            uint32_t aF[4][4], bH[4][2], bL[4][2];
            #pragma unroll
            for (int mi = 0; mi < 4; mi++) {
                uint32_t off = (uint32_t)((wm*64 + mi*16 + a_row) * GPAD + k0 + a_col) * 2;
                ldm_x4(aF[mi][0], aF[mi][1], aF[mi][2], aF[mi][3], baA + off);
            }
            #pragma unroll
            for (int ni = 0; ni < 4; ni++) {
                uint32_t off = (uint32_t)((wn*32 + ni*8 + b_row) * GPAD + k0 + b_col) * 2;
                ldm_x2(bH[ni][0], bH[ni][1], bbH + off);
                ldm_x2(bL[ni][0], bL[ni][1], bbL + off);
            }
            #pragma unroll
            for (int mi = 0; mi < 4; mi++)
                #pragma unroll
                for (int ni = 0; ni < 4; ni++) {
                    mma_f16(acc[mi][ni], aF[mi], bH[ni]);
                    mma_f16(acc[mi][ni], aF[mi], bL[ni]);
                }
        }
    }

    const int g = lane >> 2, tg = lane & 3;
    #pragma unroll
    for (int mi = 0; mi < 4; mi++) {
        const int row = m0 + wm*64 + mi*16 + g;
        #pragma unroll
        for (int ni = 0; ni < 4; ni++) {
            const int col = n0 + wn*32 + ni*8 + tg*2;
            float bv0 = bias[col], bv1 = bias[col + 1];
            float v0 = acc[mi][ni][0] + bv0, v1 = acc[mi][ni][1] + bv1;
            float v2 = acc[mi][ni][2] + bv0, v3 = acc[mi][ni][3] + bv1;
            if (RELU) { v0 = fmaxf(v0, 0.f); v1 = fmaxf(v1, 0.f); v2 = fmaxf(v2, 0.f); v3 = fmaxf(v3, 0.f); }
            if (RES) {
                const float2 r0 = *(const float2*)(res + (size_t)row * N + col);
                const float2 r1 = *(const float2*)(res + (size_t)(row + 8) * N + col);
                v0 += r0.x; v1 += r0.y; v2 += r1.x; v3 += r1.y;
            }
            v0 *= oscale; v1 *= oscale; v2 *= oscale; v3 *= oscale;
            if (OMODE == 2) {
                *(__half2*)(CF + (size_t)row * N + col)       = __floats2half2_rn(v0, v1);
                *(__half2*)(CF + (size_t)(row + 8) * N + col) = __floats2half2_rn(v2, v3);
            } else {
                *(float2*)(C + (size_t)row * N + col)       = make_float2(v0, v1);
                *(float2*)(C + (size_t)(row + 8) * N + col) = make_float2(v2, v3);
            }
        }
    }
}

// ---------------- pure-fp16 flash attention (1 mma per product) ----------------
// Br=128, Bc=64, 8 warps x 16 q-rows. Q,K,V,P single fp16, fp32 acc + fp32 softmax.
#define APAD 72
#define A_Q_B   (128*APAD*2)            // 18432
#define A_KV_B  (64*APAD*2)             // 9216 per K or V
#define A_ST_B  (2*A_KV_B)              // 18432 per stage
#define A_KV_OFF A_Q_B
#define A_MSK_OFF (A_Q_B + 2*A_ST_B)    // 55296
#define ATT_SMEM_BYTES (A_MSK_OFF + SQ*4)  // 63488

__device__ __forceinline__ void attn_issue_kv(const __half* K, const __half* V,
                                              size_t base, int kb, char* slot, int tid)
{
    int row = tid >> 2;
    int cb = (tid & 3) * 16;
    size_t o = base + (size_t)(kb * 64 + row) * DIM + cb;
    uint32_t d = smem_u32(slot) + (uint32_t)(row * APAD + cb) * 2;
    cpa16(d,            K + o); cpa16(d + 16,           K + o + 8);
    cpa16(d + A_KV_B,   V + o); cpa16(d + A_KV_B + 16,  V + o + 8);
}

__global__ void __launch_bounds__(256) attn_h_kernel(
    const __half* __restrict__ Q, const __half* __restrict__ K, const __half* __restrict__ V,
    const int* __restrict__ emask,
    __half* __restrict__ O)
{
    extern __shared__ char sm[];
    char* qslot = sm;
    float* smask = (float*)(sm + A_MSK_OFF);

    const int bh = blockIdx.x;
    const int qb = blockIdx.y;
    const int b = bh >> 4, h = bh & 15;
    const size_t base = (size_t)b * SQ * DIM + (size_t)h * HD;
    const int tid = threadIdx.x;
    const int lane = tid & 31;
    const int wid = tid >> 5;
    const int g = lane >> 2, tg = lane & 3;

    // Q load (single array)
    {
        int row = tid >> 1;
        int cb = (tid & 1) * 32;
        size_t o = base + (size_t)(qb * 128 + row) * DIM + cb;
        uint32_t d = smem_u32(qslot) + (uint32_t)(row * APAD + cb) * 2;
        #pragma unroll
        for (int c = 0; c < 4; c++) cpa16(d + c*16, Q + o + c*8);
    }
    attn_issue_kv(K, V, base, 0, sm + A_KV_OFF, tid);
    CP_COMMIT();

    for (int i = tid; i < SQ; i += 256)
        smask[i] = (emask[b * SQ + i] != 0) ? 0.f : -1.f;

    CP_WAIT(0);
    __syncthreads();

    // resident Q fragments
    uint32_t qf[4][4];
    {
        const uint32_t bq = smem_u32(qslot);
        const int a_row = lane & 15;
        const int a_col = (lane >> 4) << 3;
        #pragma unroll
        for (int kk = 0; kk < 4; kk++) {
            uint32_t off = (uint32_t)((wid*16 + a_row) * APAD + kk*16 + a_col) * 2;
            ldm_x4(qf[kk][0], qf[kk][1], qf[kk][2], qf[kk][3], bq + off);
        }
    }

    float oacc[8][4];
    #pragma unroll
    for (int d = 0; d < 8; d++)
        #pragma unroll
        for (int c = 0; c < 4; c++) oacc[d][c] = 0.f;
    float m0 = -1e30f, m1 = -1e30f, l0 = 0.f, l1 = 0.f;

    const int b_row = lane & 7;
    const int b_col = ((lane >> 3) & 1) << 3;
    const int t_row = lane & 15;

    for (int kb = 0; kb < SQ/64; kb++) {
        if (kb + 1 < SQ/64) {
            attn_issue_kv(K, V, base, kb + 1, sm + A_KV_OFF + ((kb + 1) & 1) * A_ST_B, tid);
            CP_COMMIT();
        }
        char* slot = sm + A_KV_OFF + (kb & 1) * A_ST_B;
        const uint32_t bk = smem_u32(slot);
        const uint32_t bv = bk + A_KV_B;

        // S = Q K^T (one mma per k16)
        float sacc[8][4];
        #pragma unroll
        for (int nt = 0; nt < 8; nt++)
            #pragma unroll
            for (int c = 0; c < 4; c++) sacc[nt][c] = 0.f;
        #pragma unroll
        for (int kk = 0; kk < 4; kk++) {
            uint32_t kf[8][2];
            #pragma unroll
            for (int nt = 0; nt < 8; nt++) {
                uint32_t off = (uint32_t)((nt*8 + b_row) * APAD + kk*16 + b_col) * 2;
                ldm_x2(kf[nt][0], kf[nt][1], bk + off);
            }
            #pragma unroll
            for (int nt = 0; nt < 8; nt++)
                mma_f16(sacc[nt], qf[kk], kf[nt]);
        }

        // mask + online softmax
        float mx0 = -1e30f, mx1 = -1e30f;
        #pragma unroll
        for (int nt = 0; nt < 8; nt++) {
            int col = kb*64 + nt*8 + tg*2;
            float f0 = smask[col], f1 = smask[col + 1];
            if (f0 < 0.f) { sacc[nt][0] = -1e9f; sacc[nt][2] = -1e9f; }
            if (f1 < 0.f) { sacc[nt][1] = -1e9f; sacc[nt][3] = -1e9f; }
            mx0 = fmaxf(mx0, fmaxf(sacc[nt][0], sacc[nt][1]));
            mx1 = fmaxf(mx1, fmaxf(sacc[nt][2], sacc[nt][3]));
        }
        mx0 = fmaxf(mx0, __shfl_xor_sync(0xffffffffu, mx0, 1));
        mx0 = fmaxf(mx0, __shfl_xor_sync(0xffffffffu, mx0, 2));
        mx1 = fmaxf(mx1, __shfl_xor_sync(0xffffffffu, mx1, 1));
        mx1 = fmaxf(mx1, __shfl_xor_sync(0xffffffffu, mx1, 2));
        float mn0 = fmaxf(m0, mx0), mn1 = fmaxf(m1, mx1);
        float al0 = __expf(m0 - mn0), al1 = __expf(m1 - mn1);
        float rs0 = 0.f, rs1 = 0.f;
        #pragma unroll
        for (int nt = 0; nt < 8; nt++) {
            sacc[nt][0] = __expf(sacc[nt][0] - mn0);
            sacc[nt][1] = __expf(sacc[nt][1] - mn0);
            sacc[nt][2] = __expf(sacc[nt][2] - mn1);
            sacc[nt][3] = __expf(sacc[nt][3] - mn1);
            rs0 += sacc[nt][0] + sacc[nt][1];
            rs1 += sacc[nt][2] + sacc[nt][3];
        }
        rs0 += __shfl_xor_sync(0xffffffffu, rs0, 1);
        rs0 += __shfl_xor_sync(0xffffffffu, rs0, 2);
        rs1 += __shfl_xor_sync(0xffffffffu, rs1, 1);
        rs1 += __shfl_xor_sync(0xffffffffu, rs1, 2);
        l0 = l0 * al0 + rs0; l1 = l1 * al1 + rs1;
        m0 = mn0; m1 = mn1;
        #pragma unroll
        for (int d = 0; d < 8; d++) {
            oacc[d][0] *= al0; oacc[d][1] *= al0;
            oacc[d][2] *= al1; oacc[d][3] *= al1;
        }

        // O += P V (one mma per k16)
        #pragma unroll
        for (int kk = 0; kk < 4; kk++) {
            uint32_t pf[4];
            pf[0] = pack2h(sacc[2*kk][0],   sacc[2*kk][1]);
            pf[1] = pack2h(sacc[2*kk][2],   sacc[2*kk][3]);
            pf[2] = pack2h(sacc[2*kk+1][0], sacc[2*kk+1][1]);
            pf[3] = pack2h(sacc[2*kk+1][2], sacc[2*kk+1][3]);
            uint32_t vf[8][2];
            #pragma unroll
            for (int dt = 0; dt < 8; dt++) {
                uint32_t off = (uint32_t)((kk*16 + t_row) * APAD + dt*8) * 2;
                ldm_x2t(vf[dt][0], vf[dt][1], bv + off);
            }
            #pragma unroll
            for (int dt = 0; dt < 8; dt++)
                mma_f16(oacc[dt], pf, vf[dt]);
        }

        if (kb + 1 < SQ/64) {
            CP_WAIT(0);
            __syncthreads();
        }
    }

    float il0 = 1.f / l0, il1 = 1.f / l1;
    const int r0 = qb*128 + wid*16 + g;
    const int r1 = r0 + 8;
    const size_t rowoff0 = base + (size_t)r0 * DIM;
    const size_t rowoff1 = base + (size_t)r1 * DIM;
    #pragma unroll
    for (int dt = 0; dt < 8; dt++) {
        const int col = dt*8 + tg*2;
        *(__half2*)(O + rowoff0 + col) = __floats2half2_rn(oacc[dt][0]*il0, oacc[dt][1]*il0);
        *(__half2*)(O + rowoff1 + col) = __floats2half2_rn(oacc[dt][2]*il1, oacc[dt][3]*il1);
    }
}

// ---------------- launch ----------------
extern "C" void kernel_launch(void* const* d_in, const int* in_sizes, int n_in,
                              void* d_out, int out_size)
{
    const float* x  = (const float*)d_in[0];
    const int*   em = (const int*)  d_in[1];
    const float* wq = (const float*)d_in[2];
    const float* bq = (const float*)d_in[3];
    const float* wk = (const float*)d_in[4];
    const float* bk = (const float*)d_in[5];
    const float* wv = (const float*)d_in[6];
    const float* bv = (const float*)d_in[7];
    const float* wo = (const float*)d_in[8];
    const float* bo = (const float*)d_in[9];
    const float* w1 = (const float*)d_in[10];
    const float* b1 = (const float*)d_in[11];
    const float* w2 = (const float*)d_in[12];
    const float* b2 = (const float*)d_in[13];
    const float* ga = (const float*)d_in[14];
    const float* gf = (const float*)d_in[15];
    float* out = (float*)d_out;

    __half *xn, *att, *h, *q, *k, *v;
    __half *wqH, *wqL, *wkH, *wkL, *wvH, *wvL, *woH, *woL, *w1H, *w1L, *w2H, *w2L;
    float *x1;
    cudaGetSymbolAddress((void**)&xn,  g_xn);
    cudaGetSymbolAddress((void**)&att, g_att);
    cudaGetSymbolAddress((void**)&h,   g_h);
    cudaGetSymbolAddress((void**)&q,   g_q);
    cudaGetSymbolAddress((void**)&k,   g_k);
    cudaGetSymbolAddress((void**)&v,   g_v);
    cudaGetSymbolAddress((void**)&wqH, g_wqH);  cudaGetSymbolAddress((void**)&wqL, g_wqL);
    cudaGetSymbolAddress((void**)&wkH, g_wkH);  cudaGetSymbolAddress((void**)&wkL, g_wkL);
    cudaGetSymbolAddress((void**)&wvH, g_wvH);  cudaGetSymbolAddress((void**)&wvL, g_wvL);
    cudaGetSymbolAddress((void**)&woH, g_woH);  cudaGetSymbolAddress((void**)&woL, g_woL);
    cudaGetSymbolAddress((void**)&w1H, g_w1H);  cudaGetSymbolAddress((void**)&w1L, g_w1L);
    cudaGetSymbolAddress((void**)&w2H, g_w2H);  cudaGetSymbolAddress((void**)&w2L, g_w2L);
    cudaGetSymbolAddress((void**)&x1,  g_x1);

    cudaFuncSetAttribute(attn_h_kernel, cudaFuncAttributeMaxDynamicSharedMemorySize, ATT_SMEM_BYTES);
    cudaFuncSetAttribute(gemm_h_kernel<0,0,2>, cudaFuncAttributeMaxDynamicSharedMemorySize, G_SMEM_BYTES);
    cudaFuncSetAttribute(gemm_h_kernel<1,0,2>, cudaFuncAttributeMaxDynamicSharedMemorySize, G_SMEM_BYTES);
    cudaFuncSetAttribute(gemm_h_kernel<0,1,0>, cudaFuncAttributeMaxDynamicSharedMemorySize, G_SMEM_BYTES);

    const int n1M = DIM*DIM/4, n4M = HIDDEN*DIM/4;
    split_h_kernel<<<(n1M+255)/256, 256>>>(wq, wqH, wqL, n1M);
    split_h_kernel<<<(n1M+255)/256, 256>>>(wk, wkH, wkL, n1M);
    split_h_kernel<<<(n1M+255)/256, 256>>>(wv, wvH, wvL, n1M);
    split_h_kernel<<<(n1M+255)/256, 256>>>(wo, woH, woL, n1M);
    split_h_kernel<<<(n4M+255)/256, 256>>>(w1, w1H, w1L, n4M);
    split_h_kernel<<<(n4M+255)/256, 256>>>(w2, w2H, w2L, n4M);

    dim3 gProj(DIM/128, BTOK/128);
    dim3 gFfn1(HIDDEN/128, BTOK/128);

    rmsnorm_h_kernel<<<BTOK, 256>>>(x, ga, xn);
    gemm_h_kernel<0,0,2><<<gProj, 256, G_SMEM_BYTES>>>(xn, wqH, wqL, bq, nullptr, nullptr, q, 0.125f, BTOK, DIM, DIM);
    gemm_h_kernel<0,0,2><<<gProj, 256, G_SMEM_BYTES>>>(xn, wkH, wkL, bk, nullptr, nullptr, k, 1.0f,   BTOK, DIM, DIM);
    gemm_h_kernel<0,0,2><<<gProj, 256, G_SMEM_BYTES>>>(xn, wvH, wvL, bv, nullptr, nullptr, v, 1.0f,   BTOK, DIM, DIM);
    attn_h_kernel<<<dim3(BB*NH, SQ/128), 256, ATT_SMEM_BYTES>>>(q, k, v, em, att);
    gemm_h_kernel<0,1,0><<<gProj, 256, G_SMEM_BYTES>>>(att, woH, woL, bo, x, x1, nullptr, 1.0f, BTOK, DIM, DIM);
    rmsnorm_h_kernel<<<BTOK, 256>>>(x1, gf, xn);
    gemm_h_kernel<1,0,2><<<gFfn1, 256, G_SMEM_BYTES>>>(xn, w1H, w1L, b1, nullptr, nullptr, h, 1.0f, BTOK, HIDDEN, DIM);
    gemm_h_kernel<0,1,0><<<gProj, 256, G_SMEM_BYTES>>>(h, w2H, w2L, b2, x1, out, nullptr, 1.0f, BTOK, DIM, HIDDEN);
}